// round 12
// baseline (speedup 1.0000x reference)
#include <cuda_runtime.h>
#include <math.h>

#define N 1536
#define EE 24576
#define E2 (EE + N)
#define HD 128
#define DD 1280
#define NW 48   // N/32 bitmask words per row
#define ZU 5    // split-K depth for U (K-chunk 256)

// ---------------- device scratch (no allocations allowed) ----------------
// Invariants across runs: g_cntT/g_cntS zero at entry (re-zeroed in kFill);
// g_B zeroed by kZero (event-ordered before kFill).
__device__ float g_wa[HD], g_wb[HD], g_c2[N];
__device__ float g_sa[N], g_da[N];
__device__ float g_U[HD * N];
__device__ float g_Up[ZU * HD * N];
__device__ float g_xg[N * HD];
__device__ float g_H2[N * N];
__device__ float g_H2b[N * N];
__device__ int   g_cntT[N], g_offT[N + 1], g_curT[N];
__device__ int   g_cntS[N], g_offS[N + 1], g_curS[N];
__device__ int   g_srcT[E2];
__device__ int   g_tgtS[EE];
__device__ unsigned g_B[N * NW];

__device__ __forceinline__ float lrelu(float v) { return v > 0.f ? v : 0.2f * v; }
__device__ __forceinline__ unsigned fenc(float f) {
  unsigned u = __float_as_uint(f);
  return (u & 0x80000000u) ? ~u : (u | 0x80000000u);
}

__device__ __forceinline__ float blockSum256(float v, float* sh) {
  __syncthreads();
  #pragma unroll
  for (int o = 16; o; o >>= 1) v += __shfl_xor_sync(0xFFFFFFFFu, v, o);
  if ((threadIdx.x & 31) == 0) sh[threadIdx.x >> 5] = v;
  __syncthreads();
  if (threadIdx.x < 32) {
    v = (threadIdx.x < 8) ? sh[threadIdx.x] : 0.f;
    #pragma unroll
    for (int o = 4; o; o >>= 1) v += __shfl_xor_sync(0xFFFFFFFFu, v, o);
  }
  return v;
}

// ---------- host-side fork/join resources ----------
struct HxStreams {
  cudaStream_t s1, s2, s3;
  cudaEvent_t e0, e1, e2, e3;
  HxStreams() {
    cudaStreamCreateWithFlags(&s1, cudaStreamNonBlocking);
    cudaStreamCreateWithFlags(&s2, cudaStreamNonBlocking);
    cudaStreamCreateWithFlags(&s3, cudaStreamNonBlocking);
    cudaEventCreateWithFlags(&e0, cudaEventDisableTiming);
    cudaEventCreateWithFlags(&e1, cudaEventDisableTiming);
    cudaEventCreateWithFlags(&e2, cudaEventDisableTiming);
    cudaEventCreateWithFlags(&e3, cudaEventDisableTiming);
  }
};
static HxStreams g_hs;

// ============ kZero: zero out buffer + g_B ===============
__global__ void kZero(float* __restrict__ out, int out_size) {
  int i = blockIdx.x * blockDim.x + threadIdx.x;
  int stride = gridDim.x * blockDim.x;
  for (int p = i; p < out_size; p += stride) out[p] = 0.f;
  for (int p = i; p < N * NW; p += stride) g_B[p] = 0u;
}

// ============ kCount ===================================
__global__ void kCount(const int* __restrict__ ei) {
  int idx = blockIdx.x * blockDim.x + threadIdx.x;
  if (idx < EE) {
    atomicAdd(&g_cntS[ei[idx]], 1);
    atomicAdd(&g_cntT[ei[EE + idx]], 1);
  } else if (idx < E2) {
    atomicAdd(&g_cntT[idx - EE], 1);
  }
}

// ============ kScan ========================
__global__ void kScan() {
  __shared__ int part[256];
  int tid = threadIdx.x;
  int base = tid * 6;
  {
    int a[6]; int s = 0;
    #pragma unroll
    for (int u = 0; u < 6; u++) { a[u] = g_cntT[base + u]; s += a[u]; }
    part[tid] = s;
    __syncthreads();
    for (int o = 1; o < 256; o <<= 1) {
      int v = (tid >= o) ? part[tid - o] : 0;
      __syncthreads();
      part[tid] += v;
      __syncthreads();
    }
    int excl = part[tid] - s;
    #pragma unroll
    for (int u = 0; u < 6; u++) {
      g_offT[base + u] = excl; g_curT[base + u] = excl; excl += a[u];
    }
    if (tid == 255) g_offT[N] = part[255];
    __syncthreads();
  }
  {
    int a[6]; int s = 0;
    #pragma unroll
    for (int u = 0; u < 6; u++) { a[u] = g_cntS[base + u]; s += a[u]; }
    part[tid] = s;
    __syncthreads();
    for (int o = 1; o < 256; o <<= 1) {
      int v = (tid >= o) ? part[tid - o] : 0;
      __syncthreads();
      part[tid] += v;
      __syncthreads();
    }
    int excl = part[tid] - s;
    #pragma unroll
    for (int u = 0; u < 6; u++) {
      g_offS[base + u] = excl; g_curS[base + u] = excl; excl += a[u];
    }
    if (tid == 255) g_offS[N] = part[255];
  }
}

// ============ kFill: CSR fill + B build + cnt re-zero ======================
__global__ void kFill(const int* __restrict__ ei) {
  int idx = blockIdx.x * blockDim.x + threadIdx.x;
  if (idx < N) { g_cntT[idx] = 0; g_cntS[idx] = 0; }
  if (idx >= E2) return;
  int s, t;
  if (idx < EE) { s = ei[idx]; t = ei[EE + idx]; }
  else { s = t = idx - EE; }
  int pos = atomicAdd(&g_curT[t], 1);
  g_srcT[pos] = s;
  if (idx < EE) {
    int ps = atomicAdd(&g_curS[s], 1);
    g_tgtS[ps] = t;
    atomicOr(&g_B[t * NW + (s >> 5)], 1u << (s & 31));
  }
}

// ============ kVec1 ============================
__global__ __launch_bounds__(256) void kVec1(const float* __restrict__ W1,
                                             const float* __restrict__ a1,
                                             const float* __restrict__ a2,
                                             const float* __restrict__ b1,
                                             const float* __restrict__ w2,
                                             const float* __restrict__ xo) {
  __shared__ float sh[8];
  int b = blockIdx.x, tid = threadIdx.x;
  if (b < HD) {
    float s1 = 0.f, s2 = 0.f;
    for (int d = tid; d < DD; d += 256) {
      float w = W1[b * DD + d];
      s1 += w * a1[d]; s2 += w * a2[d];
    }
    float r1 = blockSum256(s1, sh);
    float r2 = blockSum256(s2, sh);
    if (tid == 0) { g_wa[b] = r1; g_wb[b] = r2; }
  } else {
    int j = b - HD;
    float s = 0.f;
    for (int d = tid; d < DD; d += 256) s += b1[d] * w2[d] * xo[j * DD + d];
    float r = blockSum256(s, sh);
    if (tid == 0) g_c2[j] = r;
  }
}

// ============ kSada ==================================
__global__ __launch_bounds__(256) void kSada(const float* __restrict__ x) {
  int node = blockIdx.x * 8 + (threadIdx.x >> 5);
  int lane = threadIdx.x & 31;
  if (node >= N) return;
  float s1 = 0.f, s2 = 0.f;
  #pragma unroll
  for (int k = lane; k < HD; k += 32) {
    float xv = x[node * HD + k];
    s1 += xv * g_wa[k]; s2 += xv * g_wb[k];
  }
  #pragma unroll
  for (int o = 16; o; o >>= 1) {
    s1 += __shfl_xor_sync(0xFFFFFFFFu, s1, o);
    s2 += __shfl_xor_sync(0xFFFFFFFFu, s2, o);
  }
  if (lane == 0) { g_sa[node] = s1; g_da[node] = s2; }
}

// ==== kUp: U split-K partials; float4 fragments, LDS.128 inner loop ========
__global__ __launch_bounds__(256, 2) void kUp(const float* __restrict__ W1,
                                              const float* __restrict__ w2,
                                              const float* __restrict__ xo) {
  __shared__ __align__(16) float As[2][16][68];
  __shared__ __align__(16) float Bs[2][16][132];
  int b = blockIdx.x;
  int tileid = b % 24;
  int z = b / 24;
  int j0 = (tileid % 12) * 128;
  int m0 = (tileid / 12) * 64;
  int k0 = z * 256;
  int tid = threadIdx.x, tx = tid & 15, ty = tid >> 4;
  float acc[4][8];
  #pragma unroll
  for (int u = 0; u < 4; u++)
    #pragma unroll
    for (int w = 0; w < 8; w++) acc[u][w] = 0.f;
  auto load = [&](int buf, int kc) {
    #pragma unroll
    for (int l = tid; l < 64 * 16; l += 256) {
      int k = l & 15, m = l >> 4;
      As[buf][k][m] = W1[(m0 + m) * DD + k0 + kc + k] * w2[k0 + kc + k];
    }
    #pragma unroll
    for (int l = tid; l < 128 * 16; l += 256) {
      int k = l & 15, j = l >> 4;
      Bs[buf][k][j] = xo[(j0 + j) * DD + k0 + kc + k];
    }
  };
  load(0, 0);
  __syncthreads();
  for (int c = 0; c < 16; c++) {
    int buf = c & 1;
    if (c < 15) load(buf ^ 1, (c + 1) * 16);
    #pragma unroll
    for (int kk = 0; kk < 16; kk++) {
      float4 ra  = *(const float4*)&As[buf][kk][ty * 4];
      float4 rb0 = *(const float4*)&Bs[buf][kk][tx * 4];
      float4 rb1 = *(const float4*)&Bs[buf][kk][64 + tx * 4];
      float rav[4] = {ra.x, ra.y, ra.z, ra.w};
      float rbv[8] = {rb0.x, rb0.y, rb0.z, rb0.w, rb1.x, rb1.y, rb1.z, rb1.w};
      #pragma unroll
      for (int u = 0; u < 4; u++)
        #pragma unroll
        for (int w = 0; w < 8; w++) acc[u][w] = fmaf(rav[u], rbv[w], acc[u][w]);
    }
    __syncthreads();
  }
  float* Up = g_Up + z * (HD * N);
  #pragma unroll
  for (int u = 0; u < 4; u++) {
    int row = m0 + ty * 4 + u;
    *(float4*)&Up[row * N + j0 + tx * 4] =
        make_float4(acc[u][0], acc[u][1], acc[u][2], acc[u][3]);
    *(float4*)&Up[row * N + j0 + 64 + tx * 4] =
        make_float4(acc[u][4], acc[u][5], acc[u][6], acc[u][7]);
  }
}

// ============ kUred ===============================
__global__ void kUred() {
  int idx = blockIdx.x * blockDim.x + threadIdx.x;
  float s = 0.f;
  #pragma unroll
  for (int z = 0; z < ZU; z++) s += g_Up[z * (HD * N) + idx];
  g_U[idx] = s;
}

// ============ kXg: fused GAT-1 softmax + xg = P@x ==========================
__global__ __launch_bounds__(128) void kXg(const float* __restrict__ x) {
  int t = blockIdx.x, tid = threadIdx.x;
  __shared__ int   ss[256];
  __shared__ float sw[256];
  __shared__ float sh[4];
  int p0 = g_offT[t], p1 = g_offT[t + 1];
  float dt = g_da[t];
  float m = -3.4e38f;
  for (int p = p0 + tid; p < p1; p += 128)
    m = fmaxf(m, lrelu(g_sa[g_srcT[p]] + dt));
  #pragma unroll
  for (int o = 16; o; o >>= 1) m = fmaxf(m, __shfl_xor_sync(0xFFFFFFFFu, m, o));
  if ((tid & 31) == 0) sh[tid >> 5] = m;
  __syncthreads();
  m = fmaxf(fmaxf(sh[0], sh[1]), fmaxf(sh[2], sh[3]));
  float acc = 0.f, dsum = 0.f;
  for (int base = p0; base < p1; base += 256) {
    int nc = min(256, p1 - base);
    for (int q = tid; q < nc; q += 128) {
      int s = g_srcT[base + q];
      float w = expf(lrelu(g_sa[s] + dt) - m);
      ss[q] = s;
      sw[q] = w;
      dsum += w;
    }
    __syncthreads();
    for (int q = 0; q < nc; q++)
      acc += sw[q] * x[ss[q] * HD + tid];
    __syncthreads();
  }
  float den = dsum;
  #pragma unroll
  for (int o = 16; o; o >>= 1) den += __shfl_xor_sync(0xFFFFFFFFu, den, o);
  if ((tid & 31) == 0) sh[tid >> 5] = den;
  __syncthreads();
  den = sh[0] + sh[1] + sh[2] + sh[3];
  g_xg[t * HD + tid] = acc / den;
}

// ==== kH2: H2 partials = xg @ U; float4 fragments, LDS.128 inner loop ======
__global__ __launch_bounds__(256, 2) void kH2() {
  __shared__ __align__(16) float As[2][16][68];
  __shared__ __align__(16) float Bs[2][16][132];
  int b = blockIdx.x;
  int tile = b % 288;
  int z = b / 288;
  int j0 = (tile % 12) * 128;
  int m0 = (tile / 12) * 64;
  int k0 = z * 64;
  int tid = threadIdx.x, tx = tid & 15, ty = tid >> 4;
  float acc[4][8];
  #pragma unroll
  for (int u = 0; u < 4; u++)
    #pragma unroll
    for (int w = 0; w < 8; w++) acc[u][w] = 0.f;
  auto load = [&](int buf, int kc) {
    #pragma unroll
    for (int l = tid; l < 64 * 16; l += 256) {
      int k = l & 15, m = l >> 4;
      As[buf][k][m] = g_xg[(m0 + m) * HD + k0 + kc + k];
    }
    #pragma unroll
    for (int l = tid; l < 16 * 128; l += 256) {
      int j = l & 127, k = l >> 7;
      Bs[buf][k][j] = g_U[(k0 + kc + k) * N + j0 + j];
    }
  };
  load(0, 0);
  __syncthreads();
  for (int c = 0; c < 4; c++) {
    int buf = c & 1;
    if (c < 3) load(buf ^ 1, (c + 1) * 16);
    #pragma unroll
    for (int kk = 0; kk < 16; kk++) {
      float4 ra  = *(const float4*)&As[buf][kk][ty * 4];
      float4 rb0 = *(const float4*)&Bs[buf][kk][tx * 4];
      float4 rb1 = *(const float4*)&Bs[buf][kk][64 + tx * 4];
      float rav[4] = {ra.x, ra.y, ra.z, ra.w};
      float rbv[8] = {rb0.x, rb0.y, rb0.z, rb0.w, rb1.x, rb1.y, rb1.z, rb1.w};
      #pragma unroll
      for (int u = 0; u < 4; u++)
        #pragma unroll
        for (int w = 0; w < 8; w++) acc[u][w] = fmaf(rav[u], rbv[w], acc[u][w]);
    }
    __syncthreads();
  }
  float* outp = z ? g_H2b : g_H2;
  #pragma unroll
  for (int u = 0; u < 4; u++) {
    int row = m0 + ty * 4 + u;
    *(float4*)&outp[row * N + j0 + tx * 4] =
        make_float4(acc[u][0], acc[u][1], acc[u][2], acc[u][3]);
    *(float4*)&outp[row * N + j0 + 64 + tx * 4] =
        make_float4(acc[u][4], acc[u][5], acc[u][6], acc[u][7]);
  }
}

// == kF: 2-hop mask + FACTORIZED gather softmax + radix-select ==============
__global__ __launch_bounds__(256) void kF(const float* __restrict__ pas2,
                                          const float* __restrict__ pad2,
                                          const float* __restrict__ pb2,
                                          float* __restrict__ out, int wk) {
  int i = blockIdx.x, tid = threadIdx.x;
  __shared__ float v[N];
  __shared__ int vlist[N];
  __shared__ float scl[N];
  __shared__ unsigned k32[N];
  __shared__ float Ev[N];      // exp(as2*v[s] - M), valid s only
  __shared__ float E5v[N];     // exp(0.2*(as2*v[s] - M)), valid s only
  __shared__ unsigned mb[NW];
  __shared__ int wcnt[NW + 1];
  __shared__ int hist[256];
  __shared__ float shm[8];
  __shared__ unsigned s_pfx;
  __shared__ int s_rem;
  __shared__ float s_M;

  float as2 = pas2[0], ad2 = pad2[0], b2 = pb2[0];

  if (tid < NW) {
    unsigned w = g_B[i * NW + tid];
    if (tid == (i >> 5)) w |= 1u << (i & 31);
    mb[tid] = w;
  }
  for (int j = tid; j < N; j += 256)
    v[j] = g_H2[i * N + j] + g_H2b[i * N + j] + g_c2[j];
  __syncthreads();
  // 1-hop list
  if (tid < NW) wcnt[tid] = __popc(mb[tid]);
  __syncthreads();
  if (tid == 0) {
    int s = 0;
    for (int w = 0; w < NW; w++) { int c = wcnt[w]; wcnt[w] = s; s += c; }
    wcnt[NW] = s;
  }
  __syncthreads();
  int nk = wcnt[NW];
  if (tid < NW) {
    unsigned b = mb[tid]; int o = wcnt[tid];
    while (b) { int t = __ffs(b) - 1; b &= b - 1; vlist[o++] = tid * 32 + t; }
  }
  __syncthreads();
  // 2-hop
  if (tid < 4 * NW) {
    int sy = tid / NW, cx = tid % NW;
    unsigned acc = 0u;
    for (int q = sy; q < nk; q += 4) acc |= g_B[vlist[q] * NW + cx];
    atomicOr(&mb[cx], acc);
  }
  __syncthreads();
  // valid list (ascending index order — stable tie-break depends on it)
  if (tid < NW) wcnt[tid] = __popc(mb[tid]);
  __syncthreads();
  if (tid == 0) {
    int s = 0;
    for (int w = 0; w < NW; w++) { int c = wcnt[w]; wcnt[w] = s; s += c; }
    wcnt[NW] = s;
  }
  __syncthreads();
  int nvv = wcnt[NW];
  if (tid < NW) {
    unsigned b = mb[tid]; int o = wcnt[tid];
    while (b) { int t = __ffs(b) - 1; b &= b - 1; vlist[o++] = tid * 32 + t; }
  }
  __syncthreads();
  // row max M of as2*v[s] over valid s (for stable factorization)
  {
    float lm = -3.4e38f;
    for (int li = tid; li < nvv; li += 256)
      lm = fmaxf(lm, as2 * v[vlist[li]]);
    #pragma unroll
    for (int o = 16; o; o >>= 1) lm = fmaxf(lm, __shfl_xor_sync(0xFFFFFFFFu, lm, o));
    if ((tid & 31) == 0) shm[tid >> 5] = lm;
    __syncthreads();
    if (tid == 0) {
      float mm = shm[0];
      #pragma unroll
      for (int q = 1; q < 8; q++) mm = fmaxf(mm, shm[q]);
      s_M = mm;
    }
    __syncthreads();
  }
  float M = s_M;
  // per-source factors (2 exps per valid source)
  for (int li = tid; li < nvv; li += 256) {
    int s = vlist[li];
    float a = as2 * v[s] - M;        // <= 0
    Ev[s]  = __expf(a);
    E5v[s] = __expf(0.2f * a);
  }
  __syncthreads();
  // gather softmax: pass 1 max (MUFU-free), pass 2 factorized weights
  for (int li = tid; li < nvv; li += 256) {
    int t = vlist[li];
    int p0 = g_offT[t], p1 = g_offT[t + 1];
    float adt = ad2 * v[t];
    float m = -3.4e38f;
    for (int p = p0; p < p1; p++) {
      int s = g_srcT[p];
      if ((mb[s >> 5] >> (s & 31)) & 1u)
        m = fmaxf(m, lrelu(fmaf(as2, v[s], adt)));
    }
    // per-target factors (2 exps per target), clamped against overflow
    float F1 = __expf(fminf(adt + M - m, 80.f));
    float F5 = __expf(fminf(0.2f * adt + 0.2f * M - m, 80.f));
    float den = 0.f, num = 0.f;
    for (int p = p0; p < p1; p++) {
      int s = g_srcT[p];
      if ((mb[s >> 5] >> (s & 31)) & 1u) {
        float vs = v[s];
        float u = fmaf(as2, vs, adt);
        float w = (u > 0.f) ? Ev[s] * F1 : E5v[s] * F5;
        den += w;
        num = fmaf(w, vs, num);
      }
    }
    float sc = num / fmaxf(den, 1e-12f) + b2;
    scl[li] = sc;
    k32[li] = fenc(sc);
  }
  int kk = (nvv + 1) >> 1;
  if (tid == 0) { s_rem = kk; s_pfx = 0u; }
  __syncthreads();
  // radix-select the kk-th largest key (4 rounds of 8 bits)
  for (int r = 0; r < 4; r++) {
    int shift = 24 - 8 * r;
    hist[tid] = 0;
    __syncthreads();
    unsigned pfx = s_pfx;
    for (int li = tid; li < nvv; li += 256) {
      unsigned key = k32[li];
      bool cand = (r == 0) || ((key >> (shift + 8)) == pfx);
      if (cand) atomicAdd(&hist[(key >> shift) & 255], 1);
    }
    __syncthreads();
    if (tid < 32) {
      int s = 0;
      #pragma unroll
      for (int u = 0; u < 8; u++) s += hist[tid * 8 + u];
      int cum = s;
      #pragma unroll
      for (int o = 1; o < 32; o <<= 1) {
        int t2 = __shfl_down_sync(0xFFFFFFFFu, cum, o);
        if (tid + o < 32) cum += t2;
      }
      int run = cum - s;
      int rem = s_rem;
      unsigned pfxold = s_pfx;
      int fb = -1, frem = 0;
      for (int bb = tid * 8 + 7; bb >= tid * 8; bb--) {
        int h = hist[bb];
        if (run < rem && rem <= run + h) { fb = bb; frem = rem - run; }
        run += h;
      }
      __syncwarp();
      if (fb >= 0) { s_pfx = (pfxold << 8) | (unsigned)fb; s_rem = frem; }
    }
    __syncthreads();
  }
  unsigned T = s_pfx;
  int rem = s_rem;
  // keep: key > T, or key == T with tie-rank (ascending index) < rem
  for (int li = tid; li < nvv; li += 256) {
    unsigned key = k32[li];
    bool keep = key > T;
    if (!keep && key == T) {
      int cnt = 0;
      for (int l2 = 0; l2 < li; l2++) cnt += (k32[l2] == T);
      keep = cnt < rem;
    }
    if (keep) {
      int j = vlist[li];
      float sj = scl[li];
      out[i * N + j] = 1.f / (1.f + __expf(-sj));
      if (wk) out[N * N + i * N + j] = 1.f;
    }
  }
}

// ---------------- launch: forked-capture graph ----------------
extern "C" void kernel_launch(void* const* d_in, const int* in_sizes, int n_in,
                              void* d_out, int out_size) {
  const float* x   = (const float*)d_in[0];
  const float* xo  = (const float*)d_in[1];
  const int*   ei  = (const int*)d_in[2];
  const float* W1  = (const float*)d_in[4];
  const float* a1  = (const float*)d_in[5];
  const float* a2  = (const float*)d_in[6];
  const float* b1  = (const float*)d_in[7];
  const float* w2  = (const float*)d_in[8];
  const float* as2 = (const float*)d_in[9];
  const float* ad2 = (const float*)d_in[10];
  const float* b2  = (const float*)d_in[11];
  float* out = (float*)d_out;
  int wk = (out_size >= 2 * N * N) ? 1 : 0;

  cudaEventRecord(g_hs.e0, 0);
  cudaStreamWaitEvent(g_hs.s1, g_hs.e0, 0);
  cudaStreamWaitEvent(g_hs.s2, g_hs.e0, 0);
  cudaStreamWaitEvent(g_hs.s3, g_hs.e0, 0);

  // s3: zero out + g_B
  kZero<<<512, 256, 0, g_hs.s3>>>(out, out_size);
  cudaEventRecord(g_hs.e3, g_hs.s3);

  // s1: vec1 -> sada
  kVec1<<<HD + N, 256, 0, g_hs.s1>>>(W1, a1, a2, b1, w2, xo);
  kSada<<<192, 256, 0, g_hs.s1>>>(x);
  cudaEventRecord(g_hs.e1, g_hs.s1);

  // s2: U partials -> U reduce
  kUp<<<24 * ZU, 256, 0, g_hs.s2>>>(W1, w2, xo);
  kUred<<<(HD * N) / 256, 256, 0, g_hs.s2>>>();
  cudaEventRecord(g_hs.e2, g_hs.s2);

  // s0 (default): critical path
  kCount<<<E2 / 256, 256>>>(ei);
  kScan<<<1, 256>>>();
  cudaStreamWaitEvent(0, g_hs.e3, 0);   // g_B zeroed before fill's atomicOr
  kFill<<<E2 / 256, 256>>>(ei);
  cudaStreamWaitEvent(0, g_hs.e1, 0);   // sada done before xg
  kXg<<<N, 128>>>(x);
  cudaStreamWaitEvent(0, g_hs.e2, 0);   // U ready before H2
  kH2<<<576, 256>>>();
  kF<<<N, 256>>>(as2, ad2, b2, out, wk);
}

// round 13
// speedup vs baseline: 1.0913x; 1.0913x over previous
#include <cuda_runtime.h>
#include <math.h>

#define N 1536
#define EE 24576
#define E2 (EE + N)
#define HD 128
#define DD 1280
#define NW 48   // N/32 bitmask words per row
#define ZU 10   // split-K depth for U (K-chunk 128)

// ---------------- device scratch (no allocations allowed) ----------------
// Invariants across runs: g_cntT/g_cntS zero at entry (re-zeroed in kFill);
// g_B zeroed by kZero (event-ordered before kFill).
__device__ float g_wa[HD], g_wb[HD], g_c2[N];
__device__ float g_sa[N], g_da[N];
__device__ float g_U[HD * N];
__device__ float g_Up[ZU * HD * N];
__device__ float g_xg[N * HD];
__device__ float g_H2[N * N];
__device__ float g_H2b[N * N];
__device__ int   g_cntT[N], g_offT[N + 1], g_curT[N];
__device__ int   g_cntS[N], g_offS[N + 1], g_curS[N];
__device__ int   g_srcT[E2];
__device__ int   g_tgtS[EE];
__device__ unsigned g_B[N * NW];

__device__ __forceinline__ float lrelu(float v) { return v > 0.f ? v : 0.2f * v; }
__device__ __forceinline__ unsigned fenc(float f) {
  unsigned u = __float_as_uint(f);
  return (u & 0x80000000u) ? ~u : (u | 0x80000000u);
}

__device__ __forceinline__ float blockSum256(float v, float* sh) {
  __syncthreads();
  #pragma unroll
  for (int o = 16; o; o >>= 1) v += __shfl_xor_sync(0xFFFFFFFFu, v, o);
  if ((threadIdx.x & 31) == 0) sh[threadIdx.x >> 5] = v;
  __syncthreads();
  if (threadIdx.x < 32) {
    v = (threadIdx.x < 8) ? sh[threadIdx.x] : 0.f;
    #pragma unroll
    for (int o = 4; o; o >>= 1) v += __shfl_xor_sync(0xFFFFFFFFu, v, o);
  }
  return v;
}

// ---------- host-side fork/join resources ----------
struct HxStreams {
  cudaStream_t s1, s2, s3;
  cudaEvent_t e0, e1, e2, e3;
  HxStreams() {
    cudaStreamCreateWithFlags(&s1, cudaStreamNonBlocking);
    cudaStreamCreateWithFlags(&s2, cudaStreamNonBlocking);
    cudaStreamCreateWithFlags(&s3, cudaStreamNonBlocking);
    cudaEventCreateWithFlags(&e0, cudaEventDisableTiming);
    cudaEventCreateWithFlags(&e1, cudaEventDisableTiming);
    cudaEventCreateWithFlags(&e2, cudaEventDisableTiming);
    cudaEventCreateWithFlags(&e3, cudaEventDisableTiming);
  }
};
static HxStreams g_hs;

// ============ kZero: zero out buffer + g_B ===============
__global__ void kZero(float* __restrict__ out, int out_size) {
  int i = blockIdx.x * blockDim.x + threadIdx.x;
  int stride = gridDim.x * blockDim.x;
  for (int p = i; p < out_size; p += stride) out[p] = 0.f;
  for (int p = i; p < N * NW; p += stride) g_B[p] = 0u;
}

// ============ kCount ===================================
__global__ void kCount(const int* __restrict__ ei) {
  int idx = blockIdx.x * blockDim.x + threadIdx.x;
  if (idx < EE) {
    atomicAdd(&g_cntS[ei[idx]], 1);
    atomicAdd(&g_cntT[ei[EE + idx]], 1);
  } else if (idx < E2) {
    atomicAdd(&g_cntT[idx - EE], 1);
  }
}

// ============ kScan ========================
__global__ void kScan() {
  __shared__ int part[256];
  int tid = threadIdx.x;
  int base = tid * 6;
  {
    int a[6]; int s = 0;
    #pragma unroll
    for (int u = 0; u < 6; u++) { a[u] = g_cntT[base + u]; s += a[u]; }
    part[tid] = s;
    __syncthreads();
    for (int o = 1; o < 256; o <<= 1) {
      int v = (tid >= o) ? part[tid - o] : 0;
      __syncthreads();
      part[tid] += v;
      __syncthreads();
    }
    int excl = part[tid] - s;
    #pragma unroll
    for (int u = 0; u < 6; u++) {
      g_offT[base + u] = excl; g_curT[base + u] = excl; excl += a[u];
    }
    if (tid == 255) g_offT[N] = part[255];
    __syncthreads();
  }
  {
    int a[6]; int s = 0;
    #pragma unroll
    for (int u = 0; u < 6; u++) { a[u] = g_cntS[base + u]; s += a[u]; }
    part[tid] = s;
    __syncthreads();
    for (int o = 1; o < 256; o <<= 1) {
      int v = (tid >= o) ? part[tid - o] : 0;
      __syncthreads();
      part[tid] += v;
      __syncthreads();
    }
    int excl = part[tid] - s;
    #pragma unroll
    for (int u = 0; u < 6; u++) {
      g_offS[base + u] = excl; g_curS[base + u] = excl; excl += a[u];
    }
    if (tid == 255) g_offS[N] = part[255];
  }
}

// ============ kFill: CSR fill + B build + cnt re-zero ======================
__global__ void kFill(const int* __restrict__ ei) {
  int idx = blockIdx.x * blockDim.x + threadIdx.x;
  if (idx < N) { g_cntT[idx] = 0; g_cntS[idx] = 0; }
  if (idx >= E2) return;
  int s, t;
  if (idx < EE) { s = ei[idx]; t = ei[EE + idx]; }
  else { s = t = idx - EE; }
  int pos = atomicAdd(&g_curT[t], 1);
  g_srcT[pos] = s;
  if (idx < EE) {
    int ps = atomicAdd(&g_curS[s], 1);
    g_tgtS[ps] = t;
    atomicOr(&g_B[t * NW + (s >> 5)], 1u << (s & 31));
  }
}

// ============ kVec1 ============================
__global__ __launch_bounds__(256) void kVec1(const float* __restrict__ W1,
                                             const float* __restrict__ a1,
                                             const float* __restrict__ a2,
                                             const float* __restrict__ b1,
                                             const float* __restrict__ w2,
                                             const float* __restrict__ xo) {
  __shared__ float sh[8];
  int b = blockIdx.x, tid = threadIdx.x;
  if (b < HD) {
    float s1 = 0.f, s2 = 0.f;
    for (int d = tid; d < DD; d += 256) {
      float w = W1[b * DD + d];
      s1 += w * a1[d]; s2 += w * a2[d];
    }
    float r1 = blockSum256(s1, sh);
    float r2 = blockSum256(s2, sh);
    if (tid == 0) { g_wa[b] = r1; g_wb[b] = r2; }
  } else {
    int j = b - HD;
    float s = 0.f;
    for (int d = tid; d < DD; d += 256) s += b1[d] * w2[d] * xo[j * DD + d];
    float r = blockSum256(s, sh);
    if (tid == 0) g_c2[j] = r;
  }
}

// ============ kSada ==================================
__global__ __launch_bounds__(256) void kSada(const float* __restrict__ x) {
  int node = blockIdx.x * 8 + (threadIdx.x >> 5);
  int lane = threadIdx.x & 31;
  if (node >= N) return;
  float s1 = 0.f, s2 = 0.f;
  #pragma unroll
  for (int k = lane; k < HD; k += 32) {
    float xv = x[node * HD + k];
    s1 += xv * g_wa[k]; s2 += xv * g_wb[k];
  }
  #pragma unroll
  for (int o = 16; o; o >>= 1) {
    s1 += __shfl_xor_sync(0xFFFFFFFFu, s1, o);
    s2 += __shfl_xor_sync(0xFFFFFFFFu, s2, o);
  }
  if (lane == 0) { g_sa[node] = s1; g_da[node] = s2; }
}

// == kUp: U split-K partials; 64x64 tiles, 4x4 frags, 4 CTAs/SM =============
__global__ __launch_bounds__(256, 4) void kUp(const float* __restrict__ W1,
                                              const float* __restrict__ w2,
                                              const float* __restrict__ xo) {
  __shared__ __align__(16) float As[2][16][68];
  __shared__ __align__(16) float Bs[2][16][68];
  int b = blockIdx.x;
  int tileid = b % 48;          // 24 j-tiles x 2 m-tiles
  int z = b / 48;               // 0..ZU-1
  int j0 = (tileid % 24) * 64;
  int m0 = (tileid / 24) * 64;
  int k0 = z * 128;
  int tid = threadIdx.x, tx = tid & 15, ty = tid >> 4;
  float acc[4][4];
  #pragma unroll
  for (int u = 0; u < 4; u++)
    #pragma unroll
    for (int w = 0; w < 4; w++) acc[u][w] = 0.f;
  auto load = [&](int buf, int kc) {
    #pragma unroll
    for (int l = tid; l < 64 * 16; l += 256) {
      int k = l & 15, m = l >> 4;
      As[buf][k][m] = W1[(m0 + m) * DD + k0 + kc + k] * w2[k0 + kc + k];
      Bs[buf][k][m] = xo[(j0 + m) * DD + k0 + kc + k];
    }
  };
  load(0, 0);
  __syncthreads();
  for (int c = 0; c < 8; c++) {
    int buf = c & 1;
    if (c < 7) load(buf ^ 1, (c + 1) * 16);
    #pragma unroll
    for (int kk = 0; kk < 16; kk++) {
      float4 ra = *(const float4*)&As[buf][kk][ty * 4];
      float4 rb = *(const float4*)&Bs[buf][kk][tx * 4];
      float rav[4] = {ra.x, ra.y, ra.z, ra.w};
      float rbv[4] = {rb.x, rb.y, rb.z, rb.w};
      #pragma unroll
      for (int u = 0; u < 4; u++)
        #pragma unroll
        for (int w = 0; w < 4; w++) acc[u][w] = fmaf(rav[u], rbv[w], acc[u][w]);
    }
    __syncthreads();
  }
  float* Up = g_Up + z * (HD * N);
  #pragma unroll
  for (int u = 0; u < 4; u++) {
    int row = m0 + ty * 4 + u;
    *(float4*)&Up[row * N + j0 + tx * 4] =
        make_float4(acc[u][0], acc[u][1], acc[u][2], acc[u][3]);
  }
}

// ============ kUred ===============================
__global__ void kUred() {
  int idx = blockIdx.x * blockDim.x + threadIdx.x;
  float s = 0.f;
  #pragma unroll
  for (int z = 0; z < ZU; z++) s += g_Up[z * (HD * N) + idx];
  g_U[idx] = s;
}

// ============ kXg: fused GAT-1 softmax + xg = P@x ==========================
__global__ __launch_bounds__(128) void kXg(const float* __restrict__ x) {
  int t = blockIdx.x, tid = threadIdx.x;
  __shared__ int   ss[256];
  __shared__ float sw[256];
  __shared__ float sh[4];
  int p0 = g_offT[t], p1 = g_offT[t + 1];
  float dt = g_da[t];
  float m = -3.4e38f;
  for (int p = p0 + tid; p < p1; p += 128)
    m = fmaxf(m, lrelu(g_sa[g_srcT[p]] + dt));
  #pragma unroll
  for (int o = 16; o; o >>= 1) m = fmaxf(m, __shfl_xor_sync(0xFFFFFFFFu, m, o));
  if ((tid & 31) == 0) sh[tid >> 5] = m;
  __syncthreads();
  m = fmaxf(fmaxf(sh[0], sh[1]), fmaxf(sh[2], sh[3]));
  float acc = 0.f, dsum = 0.f;
  for (int base = p0; base < p1; base += 256) {
    int nc = min(256, p1 - base);
    for (int q = tid; q < nc; q += 128) {
      int s = g_srcT[base + q];
      float w = expf(lrelu(g_sa[s] + dt) - m);
      ss[q] = s;
      sw[q] = w;
      dsum += w;
    }
    __syncthreads();
    for (int q = 0; q < nc; q++)
      acc += sw[q] * x[ss[q] * HD + tid];
    __syncthreads();
  }
  float den = dsum;
  #pragma unroll
  for (int o = 16; o; o >>= 1) den += __shfl_xor_sync(0xFFFFFFFFu, den, o);
  if ((tid & 31) == 0) sh[tid >> 5] = den;
  __syncthreads();
  den = sh[0] + sh[1] + sh[2] + sh[3];
  g_xg[t * HD + tid] = acc / den;
}

// == kH2: H2 partials = xg @ U; 64x64 tiles, split-K=2, 4 CTAs/SM ===========
__global__ __launch_bounds__(256, 4) void kH2() {
  __shared__ __align__(16) float As[2][16][68];
  __shared__ __align__(16) float Bs[2][16][68];
  int b = blockIdx.x;
  int tile = b % 576;           // 24 j x 24 m
  int z = b / 576;              // 0..1
  int j0 = (tile % 24) * 64;
  int m0 = (tile / 24) * 64;
  int k0 = z * 64;
  int tid = threadIdx.x, tx = tid & 15, ty = tid >> 4;
  float acc[4][4];
  #pragma unroll
  for (int u = 0; u < 4; u++)
    #pragma unroll
    for (int w = 0; w < 4; w++) acc[u][w] = 0.f;
  auto load = [&](int buf, int kc) {
    #pragma unroll
    for (int l = tid; l < 64 * 16; l += 256) {
      int k = l & 15, m = l >> 4;
      As[buf][k][m] = g_xg[(m0 + m) * HD + k0 + kc + k];
    }
    #pragma unroll
    for (int l = tid; l < 16 * 64; l += 256) {
      int j = l & 63, k = l >> 6;
      Bs[buf][k][j] = g_U[(k0 + kc + k) * N + j0 + j];
    }
  };
  load(0, 0);
  __syncthreads();
  for (int c = 0; c < 4; c++) {
    int buf = c & 1;
    if (c < 3) load(buf ^ 1, (c + 1) * 16);
    #pragma unroll
    for (int kk = 0; kk < 16; kk++) {
      float4 ra = *(const float4*)&As[buf][kk][ty * 4];
      float4 rb = *(const float4*)&Bs[buf][kk][tx * 4];
      float rav[4] = {ra.x, ra.y, ra.z, ra.w};
      float rbv[4] = {rb.x, rb.y, rb.z, rb.w};
      #pragma unroll
      for (int u = 0; u < 4; u++)
        #pragma unroll
        for (int w = 0; w < 4; w++) acc[u][w] = fmaf(rav[u], rbv[w], acc[u][w]);
    }
    __syncthreads();
  }
  float* outp = z ? g_H2b : g_H2;
  #pragma unroll
  for (int u = 0; u < 4; u++) {
    int row = m0 + ty * 4 + u;
    *(float4*)&outp[row * N + j0 + tx * 4] =
        make_float4(acc[u][0], acc[u][1], acc[u][2], acc[u][3]);
  }
}

// == kF: 2-hop mask + FACTORIZED gather softmax + radix-select ==============
__global__ __launch_bounds__(256) void kF(const float* __restrict__ pas2,
                                          const float* __restrict__ pad2,
                                          const float* __restrict__ pb2,
                                          float* __restrict__ out, int wk) {
  int i = blockIdx.x, tid = threadIdx.x;
  __shared__ float v[N];
  __shared__ int vlist[N];
  __shared__ float scl[N];
  __shared__ unsigned k32[N];
  __shared__ float Ev[N];      // exp(as2*v[s] - M), valid s only
  __shared__ float E5v[N];     // exp(0.2*(as2*v[s] - M)), valid s only
  __shared__ unsigned mb[NW];
  __shared__ int wcnt[NW + 1];
  __shared__ int hist[256];
  __shared__ float shm[8];
  __shared__ unsigned s_pfx;
  __shared__ int s_rem;
  __shared__ float s_M;

  float as2 = pas2[0], ad2 = pad2[0], b2 = pb2[0];

  if (tid < NW) {
    unsigned w = g_B[i * NW + tid];
    if (tid == (i >> 5)) w |= 1u << (i & 31);
    mb[tid] = w;
  }
  for (int j = tid; j < N; j += 256)
    v[j] = g_H2[i * N + j] + g_H2b[i * N + j] + g_c2[j];
  __syncthreads();
  // 1-hop list
  if (tid < NW) wcnt[tid] = __popc(mb[tid]);
  __syncthreads();
  if (tid == 0) {
    int s = 0;
    for (int w = 0; w < NW; w++) { int c = wcnt[w]; wcnt[w] = s; s += c; }
    wcnt[NW] = s;
  }
  __syncthreads();
  int nk = wcnt[NW];
  if (tid < NW) {
    unsigned b = mb[tid]; int o = wcnt[tid];
    while (b) { int t = __ffs(b) - 1; b &= b - 1; vlist[o++] = tid * 32 + t; }
  }
  __syncthreads();
  // 2-hop
  if (tid < 4 * NW) {
    int sy = tid / NW, cx = tid % NW;
    unsigned acc = 0u;
    for (int q = sy; q < nk; q += 4) acc |= g_B[vlist[q] * NW + cx];
    atomicOr(&mb[cx], acc);
  }
  __syncthreads();
  // valid list (ascending index order — stable tie-break depends on it)
  if (tid < NW) wcnt[tid] = __popc(mb[tid]);
  __syncthreads();
  if (tid == 0) {
    int s = 0;
    for (int w = 0; w < NW; w++) { int c = wcnt[w]; wcnt[w] = s; s += c; }
    wcnt[NW] = s;
  }
  __syncthreads();
  int nvv = wcnt[NW];
  if (tid < NW) {
    unsigned b = mb[tid]; int o = wcnt[tid];
    while (b) { int t = __ffs(b) - 1; b &= b - 1; vlist[o++] = tid * 32 + t; }
  }
  __syncthreads();
  // row max M of as2*v[s] over valid s (for stable factorization)
  {
    float lm = -3.4e38f;
    for (int li = tid; li < nvv; li += 256)
      lm = fmaxf(lm, as2 * v[vlist[li]]);
    #pragma unroll
    for (int o = 16; o; o >>= 1) lm = fmaxf(lm, __shfl_xor_sync(0xFFFFFFFFu, lm, o));
    if ((tid & 31) == 0) shm[tid >> 5] = lm;
    __syncthreads();
    if (tid == 0) {
      float mm = shm[0];
      #pragma unroll
      for (int q = 1; q < 8; q++) mm = fmaxf(mm, shm[q]);
      s_M = mm;
    }
    __syncthreads();
  }
  float M = s_M;
  // per-source factors (2 exps per valid source)
  for (int li = tid; li < nvv; li += 256) {
    int s = vlist[li];
    float a = as2 * v[s] - M;        // <= 0
    Ev[s]  = __expf(a);
    E5v[s] = __expf(0.2f * a);
  }
  __syncthreads();
  // gather softmax: pass 1 max (MUFU-free), pass 2 factorized weights
  for (int li = tid; li < nvv; li += 256) {
    int t = vlist[li];
    int p0 = g_offT[t], p1 = g_offT[t + 1];
    float adt = ad2 * v[t];
    float m = -3.4e38f;
    for (int p = p0; p < p1; p++) {
      int s = g_srcT[p];
      if ((mb[s >> 5] >> (s & 31)) & 1u)
        m = fmaxf(m, lrelu(fmaf(as2, v[s], adt)));
    }
    // per-target factors (2 exps per target), clamped against overflow
    float F1 = __expf(fminf(adt + M - m, 80.f));
    float F5 = __expf(fminf(0.2f * adt + 0.2f * M - m, 80.f));
    float den = 0.f, num = 0.f;
    for (int p = p0; p < p1; p++) {
      int s = g_srcT[p];
      if ((mb[s >> 5] >> (s & 31)) & 1u) {
        float vs = v[s];
        float u = fmaf(as2, vs, adt);
        float w = (u > 0.f) ? Ev[s] * F1 : E5v[s] * F5;
        den += w;
        num = fmaf(w, vs, num);
      }
    }
    float sc = num / fmaxf(den, 1e-12f) + b2;
    scl[li] = sc;
    k32[li] = fenc(sc);
  }
  int kk = (nvv + 1) >> 1;
  if (tid == 0) { s_rem = kk; s_pfx = 0u; }
  __syncthreads();
  // radix-select the kk-th largest key (4 rounds of 8 bits)
  for (int r = 0; r < 4; r++) {
    int shift = 24 - 8 * r;
    hist[tid] = 0;
    __syncthreads();
    unsigned pfx = s_pfx;
    for (int li = tid; li < nvv; li += 256) {
      unsigned key = k32[li];
      bool cand = (r == 0) || ((key >> (shift + 8)) == pfx);
      if (cand) atomicAdd(&hist[(key >> shift) & 255], 1);
    }
    __syncthreads();
    if (tid < 32) {
      int s = 0;
      #pragma unroll
      for (int u = 0; u < 8; u++) s += hist[tid * 8 + u];
      int cum = s;
      #pragma unroll
      for (int o = 1; o < 32; o <<= 1) {
        int t2 = __shfl_down_sync(0xFFFFFFFFu, cum, o);
        if (tid + o < 32) cum += t2;
      }
      int run = cum - s;
      int rem = s_rem;
      unsigned pfxold = s_pfx;
      int fb = -1, frem = 0;
      for (int bb = tid * 8 + 7; bb >= tid * 8; bb--) {
        int h = hist[bb];
        if (run < rem && rem <= run + h) { fb = bb; frem = rem - run; }
        run += h;
      }
      __syncwarp();
      if (fb >= 0) { s_pfx = (pfxold << 8) | (unsigned)fb; s_rem = frem; }
    }
    __syncthreads();
  }
  unsigned T = s_pfx;
  int rem = s_rem;
  // keep: key > T, or key == T with tie-rank (ascending index) < rem
  for (int li = tid; li < nvv; li += 256) {
    unsigned key = k32[li];
    bool keep = key > T;
    if (!keep && key == T) {
      int cnt = 0;
      for (int l2 = 0; l2 < li; l2++) cnt += (k32[l2] == T);
      keep = cnt < rem;
    }
    if (keep) {
      int j = vlist[li];
      float sj = scl[li];
      out[i * N + j] = 1.f / (1.f + __expf(-sj));
      if (wk) out[N * N + i * N + j] = 1.f;
    }
  }
}

// ---------------- launch: forked-capture graph ----------------
extern "C" void kernel_launch(void* const* d_in, const int* in_sizes, int n_in,
                              void* d_out, int out_size) {
  const float* x   = (const float*)d_in[0];
  const float* xo  = (const float*)d_in[1];
  const int*   ei  = (const int*)d_in[2];
  const float* W1  = (const float*)d_in[4];
  const float* a1  = (const float*)d_in[5];
  const float* a2  = (const float*)d_in[6];
  const float* b1  = (const float*)d_in[7];
  const float* w2  = (const float*)d_in[8];
  const float* as2 = (const float*)d_in[9];
  const float* ad2 = (const float*)d_in[10];
  const float* b2  = (const float*)d_in[11];
  float* out = (float*)d_out;
  int wk = (out_size >= 2 * N * N) ? 1 : 0;

  cudaEventRecord(g_hs.e0, 0);
  cudaStreamWaitEvent(g_hs.s1, g_hs.e0, 0);
  cudaStreamWaitEvent(g_hs.s2, g_hs.e0, 0);
  cudaStreamWaitEvent(g_hs.s3, g_hs.e0, 0);

  // s3: zero out + g_B
  kZero<<<512, 256, 0, g_hs.s3>>>(out, out_size);
  cudaEventRecord(g_hs.e3, g_hs.s3);

  // s1: vec1 -> sada
  kVec1<<<HD + N, 256, 0, g_hs.s1>>>(W1, a1, a2, b1, w2, xo);
  kSada<<<192, 256, 0, g_hs.s1>>>(x);
  cudaEventRecord(g_hs.e1, g_hs.s1);

  // s2: U partials -> U reduce
  kUp<<<48 * ZU, 256, 0, g_hs.s2>>>(W1, w2, xo);
  kUred<<<(HD * N) / 256, 256, 0, g_hs.s2>>>();
  cudaEventRecord(g_hs.e2, g_hs.s2);

  // s0 (default): critical path
  kCount<<<E2 / 256, 256>>>(ei);
  kScan<<<1, 256>>>();
  cudaStreamWaitEvent(0, g_hs.e3, 0);   // g_B zeroed before fill's atomicOr
  kFill<<<E2 / 256, 256>>>(ei);
  cudaStreamWaitEvent(0, g_hs.e1, 0);   // sada done before xg
  kXg<<<N, 128>>>(x);
  cudaStreamWaitEvent(0, g_hs.e2, 0);   // U ready before H2
  kH2<<<1152, 256>>>();
  kF<<<N, 256>>>(as2, ad2, b2, out, wk);
}

// round 14
// speedup vs baseline: 1.1835x; 1.0845x over previous
#include <cuda_runtime.h>
#include <math.h>

#define N 1536
#define EE 24576
#define E2 (EE + N)
#define HD 128
#define DD 1280
#define NW 48   // N/32 bitmask words per row
#define ZU 10   // split-K depth for U (K-chunk 128)

// ---------------- device scratch (no allocations allowed) ----------------
// Invariants across runs: g_cntT/g_cntS zero at entry (re-zeroed in kFill);
// g_B zeroed by kZero (event-ordered before kFill).
__device__ float g_wa[HD], g_wb[HD], g_c2[N];
__device__ float g_sa[N], g_da[N];
__device__ float g_U[HD * N];
__device__ float g_Up[ZU * HD * N];
__device__ float g_xg[N * HD];
__device__ float g_H2[N * N];
__device__ int   g_cntT[N], g_offT[N + 1], g_curT[N];
__device__ int   g_cntS[N], g_offS[N + 1], g_curS[N];
__device__ int   g_srcT[E2];
__device__ int   g_tgtS[EE];
__device__ unsigned g_B[N * NW];

__device__ __forceinline__ float lrelu(float v) { return v > 0.f ? v : 0.2f * v; }
__device__ __forceinline__ unsigned fenc(float f) {
  unsigned u = __float_as_uint(f);
  return (u & 0x80000000u) ? ~u : (u | 0x80000000u);
}

__device__ __forceinline__ float blockSum256(float v, float* sh) {
  __syncthreads();
  #pragma unroll
  for (int o = 16; o; o >>= 1) v += __shfl_xor_sync(0xFFFFFFFFu, v, o);
  if ((threadIdx.x & 31) == 0) sh[threadIdx.x >> 5] = v;
  __syncthreads();
  if (threadIdx.x < 32) {
    v = (threadIdx.x < 8) ? sh[threadIdx.x] : 0.f;
    #pragma unroll
    for (int o = 4; o; o >>= 1) v += __shfl_xor_sync(0xFFFFFFFFu, v, o);
  }
  return v;
}

// ---------- host-side fork/join resources ----------
struct HxStreams {
  cudaStream_t s1, s2, s3;
  cudaEvent_t e0, e1, e2, e3;
  HxStreams() {
    cudaStreamCreateWithFlags(&s1, cudaStreamNonBlocking);
    cudaStreamCreateWithFlags(&s2, cudaStreamNonBlocking);
    cudaStreamCreateWithFlags(&s3, cudaStreamNonBlocking);
    cudaEventCreateWithFlags(&e0, cudaEventDisableTiming);
    cudaEventCreateWithFlags(&e1, cudaEventDisableTiming);
    cudaEventCreateWithFlags(&e2, cudaEventDisableTiming);
    cudaEventCreateWithFlags(&e3, cudaEventDisableTiming);
  }
};
static HxStreams g_hs;

// ============ kZero: zero out buffer + g_B ===============
__global__ void kZero(float* __restrict__ out, int out_size) {
  int i = blockIdx.x * blockDim.x + threadIdx.x;
  int stride = gridDim.x * blockDim.x;
  for (int p = i; p < out_size; p += stride) out[p] = 0.f;
  for (int p = i; p < N * NW; p += stride) g_B[p] = 0u;
}

// ============ kCount ===================================
__global__ void kCount(const int* __restrict__ ei) {
  int idx = blockIdx.x * blockDim.x + threadIdx.x;
  if (idx < EE) {
    atomicAdd(&g_cntS[ei[idx]], 1);
    atomicAdd(&g_cntT[ei[EE + idx]], 1);
  } else if (idx < E2) {
    atomicAdd(&g_cntT[idx - EE], 1);
  }
}

// ============ kScan ========================
__global__ void kScan() {
  __shared__ int part[256];
  int tid = threadIdx.x;
  int base = tid * 6;
  {
    int a[6]; int s = 0;
    #pragma unroll
    for (int u = 0; u < 6; u++) { a[u] = g_cntT[base + u]; s += a[u]; }
    part[tid] = s;
    __syncthreads();
    for (int o = 1; o < 256; o <<= 1) {
      int v = (tid >= o) ? part[tid - o] : 0;
      __syncthreads();
      part[tid] += v;
      __syncthreads();
    }
    int excl = part[tid] - s;
    #pragma unroll
    for (int u = 0; u < 6; u++) {
      g_offT[base + u] = excl; g_curT[base + u] = excl; excl += a[u];
    }
    if (tid == 255) g_offT[N] = part[255];
    __syncthreads();
  }
  {
    int a[6]; int s = 0;
    #pragma unroll
    for (int u = 0; u < 6; u++) { a[u] = g_cntS[base + u]; s += a[u]; }
    part[tid] = s;
    __syncthreads();
    for (int o = 1; o < 256; o <<= 1) {
      int v = (tid >= o) ? part[tid - o] : 0;
      __syncthreads();
      part[tid] += v;
      __syncthreads();
    }
    int excl = part[tid] - s;
    #pragma unroll
    for (int u = 0; u < 6; u++) {
      g_offS[base + u] = excl; g_curS[base + u] = excl; excl += a[u];
    }
    if (tid == 255) g_offS[N] = part[255];
  }
}

// ============ kFill: CSR fill + B build + cnt re-zero ======================
__global__ void kFill(const int* __restrict__ ei) {
  int idx = blockIdx.x * blockDim.x + threadIdx.x;
  if (idx < N) { g_cntT[idx] = 0; g_cntS[idx] = 0; }
  if (idx >= E2) return;
  int s, t;
  if (idx < EE) { s = ei[idx]; t = ei[EE + idx]; }
  else { s = t = idx - EE; }
  int pos = atomicAdd(&g_curT[t], 1);
  g_srcT[pos] = s;
  if (idx < EE) {
    int ps = atomicAdd(&g_curS[s], 1);
    g_tgtS[ps] = t;
    atomicOr(&g_B[t * NW + (s >> 5)], 1u << (s & 31));
  }
}

// ============ kVec1 ============================
__global__ __launch_bounds__(256) void kVec1(const float* __restrict__ W1,
                                             const float* __restrict__ a1,
                                             const float* __restrict__ a2,
                                             const float* __restrict__ b1,
                                             const float* __restrict__ w2,
                                             const float* __restrict__ xo) {
  __shared__ float sh[8];
  int b = blockIdx.x, tid = threadIdx.x;
  if (b < HD) {
    float s1 = 0.f, s2 = 0.f;
    for (int d = tid; d < DD; d += 256) {
      float w = W1[b * DD + d];
      s1 += w * a1[d]; s2 += w * a2[d];
    }
    float r1 = blockSum256(s1, sh);
    float r2 = blockSum256(s2, sh);
    if (tid == 0) { g_wa[b] = r1; g_wb[b] = r2; }
  } else {
    int j = b - HD;
    float s = 0.f;
    for (int d = tid; d < DD; d += 256) s += b1[d] * w2[d] * xo[j * DD + d];
    float r = blockSum256(s, sh);
    if (tid == 0) g_c2[j] = r;
  }
}

// ============ kSada ==================================
__global__ __launch_bounds__(256) void kSada(const float* __restrict__ x) {
  int node = blockIdx.x * 8 + (threadIdx.x >> 5);
  int lane = threadIdx.x & 31;
  if (node >= N) return;
  float s1 = 0.f, s2 = 0.f;
  #pragma unroll
  for (int k = lane; k < HD; k += 32) {
    float xv = x[node * HD + k];
    s1 += xv * g_wa[k]; s2 += xv * g_wb[k];
  }
  #pragma unroll
  for (int o = 16; o; o >>= 1) {
    s1 += __shfl_xor_sync(0xFFFFFFFFu, s1, o);
    s2 += __shfl_xor_sync(0xFFFFFFFFu, s2, o);
  }
  if (lane == 0) { g_sa[node] = s1; g_da[node] = s2; }
}

// ==== kUp: U split-K partials; 64x128 tiles, 4x8 frags (R10 best config) ===
__global__ __launch_bounds__(256, 2) void kUp(const float* __restrict__ W1,
                                              const float* __restrict__ w2,
                                              const float* __restrict__ xo) {
  __shared__ __align__(16) float As[2][16][68];
  __shared__ __align__(16) float Bs[2][16][132];
  int b = blockIdx.x;
  int tileid = b % 24;
  int z = b / 24;
  int j0 = (tileid % 12) * 128;
  int m0 = (tileid / 12) * 64;
  int k0 = z * 128;
  int tid = threadIdx.x, tx = tid & 15, ty = tid >> 4;
  float acc[4][8];
  #pragma unroll
  for (int u = 0; u < 4; u++)
    #pragma unroll
    for (int w = 0; w < 8; w++) acc[u][w] = 0.f;
  auto load = [&](int buf, int kc) {
    #pragma unroll
    for (int l = tid; l < 64 * 16; l += 256) {
      int k = l & 15, m = l >> 4;
      As[buf][k][m] = W1[(m0 + m) * DD + k0 + kc + k] * w2[k0 + kc + k];
    }
    #pragma unroll
    for (int l = tid; l < 128 * 16; l += 256) {
      int k = l & 15, j = l >> 4;
      Bs[buf][k][j] = xo[(j0 + j) * DD + k0 + kc + k];
    }
  };
  load(0, 0);
  __syncthreads();
  for (int c = 0; c < 8; c++) {
    int buf = c & 1;
    if (c < 7) load(buf ^ 1, (c + 1) * 16);
    #pragma unroll
    for (int kk = 0; kk < 16; kk++) {
      float4 ra  = *(const float4*)&As[buf][kk][ty * 4];
      float4 rb0 = *(const float4*)&Bs[buf][kk][tx * 4];
      float4 rb1 = *(const float4*)&Bs[buf][kk][64 + tx * 4];
      float rav[4] = {ra.x, ra.y, ra.z, ra.w};
      float rbv[8] = {rb0.x, rb0.y, rb0.z, rb0.w, rb1.x, rb1.y, rb1.z, rb1.w};
      #pragma unroll
      for (int u = 0; u < 4; u++)
        #pragma unroll
        for (int w = 0; w < 8; w++) acc[u][w] = fmaf(rav[u], rbv[w], acc[u][w]);
    }
    __syncthreads();
  }
  float* Up = g_Up + z * (HD * N);
  #pragma unroll
  for (int u = 0; u < 4; u++) {
    int row = m0 + ty * 4 + u;
    *(float4*)&Up[row * N + j0 + tx * 4] =
        make_float4(acc[u][0], acc[u][1], acc[u][2], acc[u][3]);
    *(float4*)&Up[row * N + j0 + 64 + tx * 4] =
        make_float4(acc[u][4], acc[u][5], acc[u][6], acc[u][7]);
  }
}

// ============ kUred ===============================
__global__ void kUred() {
  int idx = blockIdx.x * blockDim.x + threadIdx.x;
  float s = 0.f;
  #pragma unroll
  for (int z = 0; z < ZU; z++) s += g_Up[z * (HD * N) + idx];
  g_U[idx] = s;
}

// ============ kXg: fused GAT-1 softmax + xg = P@x ==========================
__global__ __launch_bounds__(128) void kXg(const float* __restrict__ x) {
  int t = blockIdx.x, tid = threadIdx.x;
  __shared__ int   ss[256];
  __shared__ float sw[256];
  __shared__ float sh[4];
  int p0 = g_offT[t], p1 = g_offT[t + 1];
  float dt = g_da[t];
  float m = -3.4e38f;
  for (int p = p0 + tid; p < p1; p += 128)
    m = fmaxf(m, lrelu(g_sa[g_srcT[p]] + dt));
  #pragma unroll
  for (int o = 16; o; o >>= 1) m = fmaxf(m, __shfl_xor_sync(0xFFFFFFFFu, m, o));
  if ((tid & 31) == 0) sh[tid >> 5] = m;
  __syncthreads();
  m = fmaxf(fmaxf(sh[0], sh[1]), fmaxf(sh[2], sh[3]));
  float acc = 0.f, dsum = 0.f;
  for (int base = p0; base < p1; base += 256) {
    int nc = min(256, p1 - base);
    for (int q = tid; q < nc; q += 128) {
      int s = g_srcT[base + q];
      float w = expf(lrelu(g_sa[s] + dt) - m);
      ss[q] = s;
      sw[q] = w;
      dsum += w;
    }
    __syncthreads();
    for (int q = 0; q < nc; q++)
      acc += sw[q] * x[ss[q] * HD + tid];
    __syncthreads();
  }
  float den = dsum;
  #pragma unroll
  for (int o = 16; o; o >>= 1) den += __shfl_xor_sync(0xFFFFFFFFu, den, o);
  if ((tid & 31) == 0) sh[tid >> 5] = den;
  __syncthreads();
  den = sh[0] + sh[1] + sh[2] + sh[3];
  g_xg[t * HD + tid] = acc / den;
}

// == kH2: H2 = xg @ U; 64x64 tiles, full K, 4 CTAs/SM, single buffer ========
__global__ __launch_bounds__(256, 4) void kH2() {
  __shared__ __align__(16) float As[2][16][68];
  __shared__ __align__(16) float Bs[2][16][68];
  int b = blockIdx.x;
  int j0 = (b % 24) * 64;
  int m0 = (b / 24) * 64;
  int tid = threadIdx.x, tx = tid & 15, ty = tid >> 4;
  float acc[4][4];
  #pragma unroll
  for (int u = 0; u < 4; u++)
    #pragma unroll
    for (int w = 0; w < 4; w++) acc[u][w] = 0.f;
  auto load = [&](int buf, int kc) {
    #pragma unroll
    for (int l = tid; l < 64 * 16; l += 256) {
      int k = l & 15, m = l >> 4;
      As[buf][k][m] = g_xg[(m0 + m) * HD + kc + k];
    }
    #pragma unroll
    for (int l = tid; l < 16 * 64; l += 256) {
      int j = l & 63, k = l >> 6;
      Bs[buf][k][j] = g_U[(kc + k) * N + j0 + j];
    }
  };
  load(0, 0);
  __syncthreads();
  for (int c = 0; c < 8; c++) {
    int buf = c & 1;
    if (c < 7) load(buf ^ 1, (c + 1) * 16);
    #pragma unroll
    for (int kk = 0; kk < 16; kk++) {
      float4 ra = *(const float4*)&As[buf][kk][ty * 4];
      float4 rb = *(const float4*)&Bs[buf][kk][tx * 4];
      float rav[4] = {ra.x, ra.y, ra.z, ra.w};
      float rbv[4] = {rb.x, rb.y, rb.z, rb.w};
      #pragma unroll
      for (int u = 0; u < 4; u++)
        #pragma unroll
        for (int w = 0; w < 4; w++) acc[u][w] = fmaf(rav[u], rbv[w], acc[u][w]);
    }
    __syncthreads();
  }
  #pragma unroll
  for (int u = 0; u < 4; u++) {
    int row = m0 + ty * 4 + u;
    *(float4*)&g_H2[row * N + j0 + tx * 4] =
        make_float4(acc[u][0], acc[u][1], acc[u][2], acc[u][3]);
  }
}

// == kF: 2-hop mask + SINGLE-PASS factorized gather softmax + radix-select ==
__global__ __launch_bounds__(256) void kF(const float* __restrict__ pas2,
                                          const float* __restrict__ pad2,
                                          const float* __restrict__ pb2,
                                          float* __restrict__ out, int wk) {
  int i = blockIdx.x, tid = threadIdx.x;
  __shared__ float v[N];
  __shared__ int vlist[N];
  __shared__ float scl[N];
  __shared__ unsigned k32[N];
  __shared__ float Ev[N];      // exp(as2*v[s] - M), valid s only
  __shared__ float E5v[N];     // exp(0.2*(as2*v[s] - M)), valid s only
  __shared__ unsigned mb[NW];
  __shared__ int wcnt[NW + 1];
  __shared__ int hist[256];
  __shared__ float shm[8];
  __shared__ unsigned s_pfx;
  __shared__ int s_rem;
  __shared__ float s_M;

  float as2 = pas2[0], ad2 = pad2[0], b2 = pb2[0];

  if (tid < NW) {
    unsigned w = g_B[i * NW + tid];
    if (tid == (i >> 5)) w |= 1u << (i & 31);
    mb[tid] = w;
  }
  {
    const float4* h2a = (const float4*)(g_H2 + i * N);
    const float4* c2v = (const float4*)g_c2;
    float4* vv = (float4*)v;
    for (int j = tid; j < N / 4; j += 256) {
      float4 a = h2a[j], c = c2v[j];
      vv[j] = make_float4(a.x + c.x, a.y + c.y, a.z + c.z, a.w + c.w);
    }
  }
  __syncthreads();
  // 1-hop list
  if (tid < NW) wcnt[tid] = __popc(mb[tid]);
  __syncthreads();
  if (tid == 0) {
    int s = 0;
    for (int w = 0; w < NW; w++) { int c = wcnt[w]; wcnt[w] = s; s += c; }
    wcnt[NW] = s;
  }
  __syncthreads();
  int nk = wcnt[NW];
  if (tid < NW) {
    unsigned b = mb[tid]; int o = wcnt[tid];
    while (b) { int t = __ffs(b) - 1; b &= b - 1; vlist[o++] = tid * 32 + t; }
  }
  __syncthreads();
  // 2-hop
  if (tid < 4 * NW) {
    int sy = tid / NW, cx = tid % NW;
    unsigned acc = 0u;
    for (int q = sy; q < nk; q += 4) acc |= g_B[vlist[q] * NW + cx];
    atomicOr(&mb[cx], acc);
  }
  __syncthreads();
  // valid list (ascending index order — stable tie-break depends on it)
  if (tid < NW) wcnt[tid] = __popc(mb[tid]);
  __syncthreads();
  if (tid == 0) {
    int s = 0;
    for (int w = 0; w < NW; w++) { int c = wcnt[w]; wcnt[w] = s; s += c; }
    wcnt[NW] = s;
  }
  __syncthreads();
  int nvv = wcnt[NW];
  if (tid < NW) {
    unsigned b = mb[tid]; int o = wcnt[tid];
    while (b) { int t = __ffs(b) - 1; b &= b - 1; vlist[o++] = tid * 32 + t; }
  }
  __syncthreads();
  // row max M of as2*v[s] over valid s (for stable factorization)
  {
    float lm = -3.4e38f;
    for (int li = tid; li < nvv; li += 256)
      lm = fmaxf(lm, as2 * v[vlist[li]]);
    #pragma unroll
    for (int o = 16; o; o >>= 1) lm = fmaxf(lm, __shfl_xor_sync(0xFFFFFFFFu, lm, o));
    if ((tid & 31) == 0) shm[tid >> 5] = lm;
    __syncthreads();
    if (tid == 0) {
      float mm = shm[0];
      #pragma unroll
      for (int q = 1; q < 8; q++) mm = fmaxf(mm, shm[q]);
      s_M = mm;
    }
    __syncthreads();
  }
  float M = s_M;
  // per-source factors (2 exps per valid source)
  for (int li = tid; li < nvv; li += 256) {
    int s = vlist[li];
    float a = as2 * v[s] - M;        // <= 0
    Ev[s]  = __expf(a);
    E5v[s] = __expf(0.2f * a);
  }
  __syncthreads();
  // SINGLE-PASS gather softmax: offset m = max(adt+M, 0) bounds all exponents
  // below 0 (pos branch: e <= M+adt <= m; neg branch: e <= 0 <= m), and the
  // num/den ratio is offset-invariant. Rare deep-underflow rows fall back to
  // the exact two-pass path.
  for (int li = tid; li < nvv; li += 256) {
    int t = vlist[li];
    int p0 = g_offT[t], p1 = g_offT[t + 1];
    float adt = ad2 * v[t];
    float am = adt + M;
    float m = fmaxf(am, 0.f);
    float F1 = __expf(am - m);
    float F5 = __expf(0.2f * am - m);
    float den = 0.f, num = 0.f;
    for (int p = p0; p < p1; p++) {
      int s = g_srcT[p];
      if ((mb[s >> 5] >> (s & 31)) & 1u) {
        float vs = v[s];
        float u = fmaf(as2, vs, adt);
        float w = (u > 0.f) ? Ev[s] * F1 : E5v[s] * F5;
        den += w;
        num = fmaf(w, vs, num);
      }
    }
    if (den < 1e-30f) {
      // exact fallback: per-target max, two passes (rare)
      float mm = -3.4e38f;
      for (int p = p0; p < p1; p++) {
        int s = g_srcT[p];
        if ((mb[s >> 5] >> (s & 31)) & 1u)
          mm = fmaxf(mm, lrelu(fmaf(as2, v[s], adt)));
      }
      den = 0.f; num = 0.f;
      for (int p = p0; p < p1; p++) {
        int s = g_srcT[p];
        if ((mb[s >> 5] >> (s & 31)) & 1u) {
          float vs = v[s];
          float w = __expf(lrelu(fmaf(as2, vs, adt)) - mm);
          den += w;
          num = fmaf(w, vs, num);
        }
      }
    }
    float sc = num / fmaxf(den, 1e-12f) + b2;
    scl[li] = sc;
    k32[li] = fenc(sc);
  }
  int kk = (nvv + 1) >> 1;
  if (tid == 0) { s_rem = kk; s_pfx = 0u; }
  __syncthreads();
  // radix-select the kk-th largest key (4 rounds of 8 bits)
  for (int r = 0; r < 4; r++) {
    int shift = 24 - 8 * r;
    hist[tid] = 0;
    __syncthreads();
    unsigned pfx = s_pfx;
    for (int li = tid; li < nvv; li += 256) {
      unsigned key = k32[li];
      bool cand = (r == 0) || ((key >> (shift + 8)) == pfx);
      if (cand) atomicAdd(&hist[(key >> shift) & 255], 1);
    }
    __syncthreads();
    if (tid < 32) {
      int s = 0;
      #pragma unroll
      for (int u = 0; u < 8; u++) s += hist[tid * 8 + u];
      int cum = s;
      #pragma unroll
      for (int o = 1; o < 32; o <<= 1) {
        int t2 = __shfl_down_sync(0xFFFFFFFFu, cum, o);
        if (tid + o < 32) cum += t2;
      }
      int run = cum - s;
      int rem = s_rem;
      unsigned pfxold = s_pfx;
      int fb = -1, frem = 0;
      for (int bb = tid * 8 + 7; bb >= tid * 8; bb--) {
        int h = hist[bb];
        if (run < rem && rem <= run + h) { fb = bb; frem = rem - run; }
        run += h;
      }
      __syncwarp();
      if (fb >= 0) { s_pfx = (pfxold << 8) | (unsigned)fb; s_rem = frem; }
    }
    __syncthreads();
  }
  unsigned T = s_pfx;
  int rem = s_rem;
  // keep: key > T, or key == T with tie-rank (ascending index) < rem
  for (int li = tid; li < nvv; li += 256) {
    unsigned key = k32[li];
    bool keep = key > T;
    if (!keep && key == T) {
      int cnt = 0;
      for (int l2 = 0; l2 < li; l2++) cnt += (k32[l2] == T);
      keep = cnt < rem;
    }
    if (keep) {
      int j = vlist[li];
      float sj = scl[li];
      out[i * N + j] = 1.f / (1.f + __expf(-sj));
      if (wk) out[N * N + i * N + j] = 1.f;
    }
  }
}

// ---------------- launch: forked-capture graph ----------------
extern "C" void kernel_launch(void* const* d_in, const int* in_sizes, int n_in,
                              void* d_out, int out_size) {
  const float* x   = (const float*)d_in[0];
  const float* xo  = (const float*)d_in[1];
  const int*   ei  = (const int*)d_in[2];
  const float* W1  = (const float*)d_in[4];
  const float* a1  = (const float*)d_in[5];
  const float* a2  = (const float*)d_in[6];
  const float* b1  = (const float*)d_in[7];
  const float* w2  = (const float*)d_in[8];
  const float* as2 = (const float*)d_in[9];
  const float* ad2 = (const float*)d_in[10];
  const float* b2  = (const float*)d_in[11];
  float* out = (float*)d_out;
  int wk = (out_size >= 2 * N * N) ? 1 : 0;

  cudaEventRecord(g_hs.e0, 0);
  cudaStreamWaitEvent(g_hs.s1, g_hs.e0, 0);
  cudaStreamWaitEvent(g_hs.s2, g_hs.e0, 0);
  cudaStreamWaitEvent(g_hs.s3, g_hs.e0, 0);

  // s3: zero out + g_B
  kZero<<<512, 256, 0, g_hs.s3>>>(out, out_size);
  cudaEventRecord(g_hs.e3, g_hs.s3);

  // s1: vec1 -> sada
  kVec1<<<HD + N, 256, 0, g_hs.s1>>>(W1, a1, a2, b1, w2, xo);
  kSada<<<192, 256, 0, g_hs.s1>>>(x);
  cudaEventRecord(g_hs.e1, g_hs.s1);

  // s2: U partials -> U reduce
  kUp<<<24 * ZU, 256, 0, g_hs.s2>>>(W1, w2, xo);
  kUred<<<(HD * N) / 256, 256, 0, g_hs.s2>>>();
  cudaEventRecord(g_hs.e2, g_hs.s2);

  // s0 (default): critical path
  kCount<<<E2 / 256, 256>>>(ei);
  kScan<<<1, 256>>>();
  cudaStreamWaitEvent(0, g_hs.e3, 0);   // g_B zeroed before fill's atomicOr
  kFill<<<E2 / 256, 256>>>(ei);
  cudaStreamWaitEvent(0, g_hs.e1, 0);   // sada done before xg
  kXg<<<N, 128>>>(x);
  cudaStreamWaitEvent(0, g_hs.e2, 0);   // U ready before H2
  kH2<<<576, 256>>>();
  kF<<<N, 256>>>(as2, ad2, b2, out, wk);
}

// round 15
// speedup vs baseline: 1.2768x; 1.0788x over previous
#include <cuda_runtime.h>
#include <cuda_bf16.h>
#include <mma.h>
#include <math.h>

using namespace nvcuda;

#define N 1536
#define EE 24576
#define E2 (EE + N)
#define HD 128
#define DD 1280
#define NW 48   // N/32 bitmask words per row
#define ZU 10   // split-K depth for U (K-chunk 128)

// ---------------- device scratch (no allocations allowed) ----------------
__device__ float g_wa[HD], g_wb[HD], g_c2[N];
__device__ float g_sa[N], g_da[N];
__device__ float g_U[HD * N];
__device__ float g_Up[ZU * HD * N];
__device__ float g_xg[N * HD];
__device__ float g_H2[N * N];
__device__ int   g_cntT[N], g_offT[N + 1], g_curT[N];
__device__ int   g_cntS[N], g_offS[N + 1], g_curS[N];
__device__ int   g_srcT[E2];
__device__ int   g_tgtS[EE];
__device__ __align__(16) unsigned g_B[N * NW];

__device__ __forceinline__ float lrelu(float v) { return v > 0.f ? v : 0.2f * v; }
__device__ __forceinline__ unsigned fenc(float f) {
  unsigned u = __float_as_uint(f);
  return (u & 0x80000000u) ? ~u : (u | 0x80000000u);
}

__device__ __forceinline__ float blockSum256(float v, float* sh) {
  __syncthreads();
  #pragma unroll
  for (int o = 16; o; o >>= 1) v += __shfl_xor_sync(0xFFFFFFFFu, v, o);
  if ((threadIdx.x & 31) == 0) sh[threadIdx.x >> 5] = v;
  __syncthreads();
  if (threadIdx.x < 32) {
    v = (threadIdx.x < 8) ? sh[threadIdx.x] : 0.f;
    #pragma unroll
    for (int o = 4; o; o >>= 1) v += __shfl_xor_sync(0xFFFFFFFFu, v, o);
  }
  return v;
}

// ---------- host-side fork/join resources ----------
struct HxStreams {
  cudaStream_t s1, s2, s3;
  cudaEvent_t e0, e1, e2, e3;
  HxStreams() {
    cudaStreamCreateWithFlags(&s1, cudaStreamNonBlocking);
    cudaStreamCreateWithFlags(&s2, cudaStreamNonBlocking);
    cudaStreamCreateWithFlags(&s3, cudaStreamNonBlocking);
    cudaEventCreateWithFlags(&e0, cudaEventDisableTiming);
    cudaEventCreateWithFlags(&e1, cudaEventDisableTiming);
    cudaEventCreateWithFlags(&e2, cudaEventDisableTiming);
    cudaEventCreateWithFlags(&e3, cudaEventDisableTiming);
  }
};
static HxStreams g_hs;

// ============ kZero: zero out buffer + g_B ===============
__global__ void kZero(float* __restrict__ out, int out_size) {
  int i = blockIdx.x * blockDim.x + threadIdx.x;
  int stride = gridDim.x * blockDim.x;
  for (int p = i; p < out_size; p += stride) out[p] = 0.f;
  for (int p = i; p < N * NW; p += stride) g_B[p] = 0u;
}

// ============ kCount ===================================
__global__ void kCount(const int* __restrict__ ei) {
  int idx = blockIdx.x * blockDim.x + threadIdx.x;
  if (idx < EE) {
    atomicAdd(&g_cntS[ei[idx]], 1);
    atomicAdd(&g_cntT[ei[EE + idx]], 1);
  } else if (idx < E2) {
    atomicAdd(&g_cntT[idx - EE], 1);
  }
}

// ============ kScan ========================
__global__ void kScan() {
  __shared__ int part[256];
  int tid = threadIdx.x;
  int base = tid * 6;
  {
    int a[6]; int s = 0;
    #pragma unroll
    for (int u = 0; u < 6; u++) { a[u] = g_cntT[base + u]; s += a[u]; }
    part[tid] = s;
    __syncthreads();
    for (int o = 1; o < 256; o <<= 1) {
      int v = (tid >= o) ? part[tid - o] : 0;
      __syncthreads();
      part[tid] += v;
      __syncthreads();
    }
    int excl = part[tid] - s;
    #pragma unroll
    for (int u = 0; u < 6; u++) {
      g_offT[base + u] = excl; g_curT[base + u] = excl; excl += a[u];
    }
    if (tid == 255) g_offT[N] = part[255];
    __syncthreads();
  }
  {
    int a[6]; int s = 0;
    #pragma unroll
    for (int u = 0; u < 6; u++) { a[u] = g_cntS[base + u]; s += a[u]; }
    part[tid] = s;
    __syncthreads();
    for (int o = 1; o < 256; o <<= 1) {
      int v = (tid >= o) ? part[tid - o] : 0;
      __syncthreads();
      part[tid] += v;
      __syncthreads();
    }
    int excl = part[tid] - s;
    #pragma unroll
    for (int u = 0; u < 6; u++) {
      g_offS[base + u] = excl; g_curS[base + u] = excl; excl += a[u];
    }
    if (tid == 255) g_offS[N] = part[255];
  }
}

// ============ kFill: CSR fill + B build + cnt re-zero ======================
__global__ void kFill(const int* __restrict__ ei) {
  int idx = blockIdx.x * blockDim.x + threadIdx.x;
  if (idx < N) { g_cntT[idx] = 0; g_cntS[idx] = 0; }
  if (idx >= E2) return;
  int s, t;
  if (idx < EE) { s = ei[idx]; t = ei[EE + idx]; }
  else { s = t = idx - EE; }
  int pos = atomicAdd(&g_curT[t], 1);
  g_srcT[pos] = s;
  if (idx < EE) {
    int ps = atomicAdd(&g_curS[s], 1);
    g_tgtS[ps] = t;
    atomicOr(&g_B[t * NW + (s >> 5)], 1u << (s & 31));
  }
}

// ============ kVec1 ============================
__global__ __launch_bounds__(256) void kVec1(const float* __restrict__ W1,
                                             const float* __restrict__ a1,
                                             const float* __restrict__ a2,
                                             const float* __restrict__ b1,
                                             const float* __restrict__ w2,
                                             const float* __restrict__ xo) {
  __shared__ float sh[8];
  int b = blockIdx.x, tid = threadIdx.x;
  if (b < HD) {
    float s1 = 0.f, s2 = 0.f;
    for (int d = tid; d < DD; d += 256) {
      float w = W1[b * DD + d];
      s1 += w * a1[d]; s2 += w * a2[d];
    }
    float r1 = blockSum256(s1, sh);
    float r2 = blockSum256(s2, sh);
    if (tid == 0) { g_wa[b] = r1; g_wb[b] = r2; }
  } else {
    int j = b - HD;
    float s = 0.f;
    for (int d = tid; d < DD; d += 256) s += b1[d] * w2[d] * xo[j * DD + d];
    float r = blockSum256(s, sh);
    if (tid == 0) g_c2[j] = r;
  }
}

// ============ kSada ==================================
__global__ __launch_bounds__(256) void kSada(const float* __restrict__ x) {
  int node = blockIdx.x * 8 + (threadIdx.x >> 5);
  int lane = threadIdx.x & 31;
  if (node >= N) return;
  float s1 = 0.f, s2 = 0.f;
  #pragma unroll
  for (int k = lane; k < HD; k += 32) {
    float xv = x[node * HD + k];
    s1 += xv * g_wa[k]; s2 += xv * g_wb[k];
  }
  #pragma unroll
  for (int o = 16; o; o >>= 1) {
    s1 += __shfl_xor_sync(0xFFFFFFFFu, s1, o);
    s2 += __shfl_xor_sync(0xFFFFFFFFu, s2, o);
  }
  if (lane == 0) { g_sa[node] = s1; g_da[node] = s2; }
}

// == kUp: U split-K partials via WMMA bf16 3-term split (hi*hi+hi*lo+lo*hi) ==
// U = (W1 .* w2) @ xo^T.  64x64 output tile, 8 warps (4x2 of 16x32 warp-tiles).
__global__ __launch_bounds__(256, 2) void kUp(const float* __restrict__ W1,
                                              const float* __restrict__ w2,
                                              const float* __restrict__ xo) {
  __shared__ __align__(16) __nv_bfloat16 Ah[64][72];
  __shared__ __align__(16) __nv_bfloat16 Al[64][72];
  __shared__ __align__(16) __nv_bfloat16 Bh[64][72];
  __shared__ __align__(16) __nv_bfloat16 Bl[64][72];
  int b = blockIdx.x;
  int tileid = b % 48;          // 24 j-tiles x 2 m-tiles
  int z = b / 48;               // 0..ZU-1, K-chunk 128
  int j0 = (tileid % 24) * 64;
  int m0 = (tileid / 24) * 64;
  int k0 = z * 128;
  int tid = threadIdx.x;
  int wid = tid >> 5;
  int wm = wid >> 1;            // 0..3  (16 rows each)
  int wn = wid & 1;             // 0..1  (32 cols each)

  wmma::fragment<wmma::accumulator, 16, 16, 16, float> acc[2];
  wmma::fill_fragment(acc[0], 0.f);
  wmma::fill_fragment(acc[1], 0.f);

  for (int kc = 0; kc < 128; kc += 64) {
    // load + split into smem (A[m][k], B[n][k]; B col_major view = xo row-major)
    for (int l = tid; l < 64 * 64; l += 256) {
      int k = l & 63, r = l >> 6;
      float av = W1[(m0 + r) * DD + k0 + kc + k] * w2[k0 + kc + k];
      __nv_bfloat16 h = __float2bfloat16(av);
      Ah[r][k] = h;
      Al[r][k] = __float2bfloat16(av - __bfloat162float(h));
      float bv = xo[(j0 + r) * DD + k0 + kc + k];
      h = __float2bfloat16(bv);
      Bh[r][k] = h;
      Bl[r][k] = __float2bfloat16(bv - __bfloat162float(h));
    }
    __syncthreads();
    #pragma unroll
    for (int kk = 0; kk < 64; kk += 16) {
      wmma::fragment<wmma::matrix_a, 16, 16, 16, __nv_bfloat16, wmma::row_major> ah, al;
      wmma::load_matrix_sync(ah, &Ah[wm * 16][kk], 72);
      wmma::load_matrix_sync(al, &Al[wm * 16][kk], 72);
      #pragma unroll
      for (int t = 0; t < 2; t++) {
        int n = wn * 32 + t * 16;
        wmma::fragment<wmma::matrix_b, 16, 16, 16, __nv_bfloat16, wmma::col_major> bh, bl;
        wmma::load_matrix_sync(bh, &Bh[n][kk], 72);
        wmma::load_matrix_sync(bl, &Bl[n][kk], 72);
        wmma::mma_sync(acc[t], ah, bh, acc[t]);
        wmma::mma_sync(acc[t], ah, bl, acc[t]);
        wmma::mma_sync(acc[t], al, bh, acc[t]);
      }
    }
    __syncthreads();
  }
  float* Up = g_Up + z * (HD * N);
  #pragma unroll
  for (int t = 0; t < 2; t++)
    wmma::store_matrix_sync(&Up[(m0 + wm * 16) * N + j0 + wn * 32 + t * 16],
                            acc[t], N, wmma::mem_row_major);
}

// ============ kUred ===============================
__global__ void kUred() {
  int idx = blockIdx.x * blockDim.x + threadIdx.x;
  float s = 0.f;
  #pragma unroll
  for (int z = 0; z < ZU; z++) s += g_Up[z * (HD * N) + idx];
  g_U[idx] = s;
}

// ============ kXg: fused GAT-1 softmax + xg = P@x ==========================
__global__ __launch_bounds__(128) void kXg(const float* __restrict__ x) {
  int t = blockIdx.x, tid = threadIdx.x;
  __shared__ int   ss[256];
  __shared__ float sw[256];
  __shared__ float sh[4];
  int p0 = g_offT[t], p1 = g_offT[t + 1];
  float dt = g_da[t];
  float m = -3.4e38f;
  for (int p = p0 + tid; p < p1; p += 128)
    m = fmaxf(m, lrelu(g_sa[g_srcT[p]] + dt));
  #pragma unroll
  for (int o = 16; o; o >>= 1) m = fmaxf(m, __shfl_xor_sync(0xFFFFFFFFu, m, o));
  if ((tid & 31) == 0) sh[tid >> 5] = m;
  __syncthreads();
  m = fmaxf(fmaxf(sh[0], sh[1]), fmaxf(sh[2], sh[3]));
  float acc = 0.f, dsum = 0.f;
  for (int base = p0; base < p1; base += 256) {
    int nc = min(256, p1 - base);
    for (int q = tid; q < nc; q += 128) {
      int s = g_srcT[base + q];
      float w = expf(lrelu(g_sa[s] + dt) - m);
      ss[q] = s;
      sw[q] = w;
      dsum += w;
    }
    __syncthreads();
    for (int q = 0; q < nc; q++)
      acc += sw[q] * x[ss[q] * HD + tid];
    __syncthreads();
  }
  float den = dsum;
  #pragma unroll
  for (int o = 16; o; o >>= 1) den += __shfl_xor_sync(0xFFFFFFFFu, den, o);
  if ((tid & 31) == 0) sh[tid >> 5] = den;
  __syncthreads();
  den = sh[0] + sh[1] + sh[2] + sh[3];
  g_xg[t * HD + tid] = acc / den;
}

// == kH2: H2 = xg @ U; 64x64 tiles, full K, 4 CTAs/SM, single buffer ========
__global__ __launch_bounds__(256, 4) void kH2() {
  __shared__ __align__(16) float As[2][16][68];
  __shared__ __align__(16) float Bs[2][16][68];
  int b = blockIdx.x;
  int j0 = (b % 24) * 64;
  int m0 = (b / 24) * 64;
  int tid = threadIdx.x, tx = tid & 15, ty = tid >> 4;
  float acc[4][4];
  #pragma unroll
  for (int u = 0; u < 4; u++)
    #pragma unroll
    for (int w = 0; w < 4; w++) acc[u][w] = 0.f;
  auto load = [&](int buf, int kc) {
    #pragma unroll
    for (int l = tid; l < 64 * 16; l += 256) {
      int k = l & 15, m = l >> 4;
      As[buf][k][m] = g_xg[(m0 + m) * HD + kc + k];
    }
    #pragma unroll
    for (int l = tid; l < 16 * 64; l += 256) {
      int j = l & 63, k = l >> 6;
      Bs[buf][k][j] = g_U[(kc + k) * N + j0 + j];
    }
  };
  load(0, 0);
  __syncthreads();
  for (int c = 0; c < 8; c++) {
    int buf = c & 1;
    if (c < 7) load(buf ^ 1, (c + 1) * 16);
    #pragma unroll
    for (int kk = 0; kk < 16; kk++) {
      float4 ra = *(const float4*)&As[buf][kk][ty * 4];
      float4 rb = *(const float4*)&Bs[buf][kk][tx * 4];
      float rav[4] = {ra.x, ra.y, ra.z, ra.w};
      float rbv[4] = {rb.x, rb.y, rb.z, rb.w};
      #pragma unroll
      for (int u = 0; u < 4; u++)
        #pragma unroll
        for (int w = 0; w < 4; w++) acc[u][w] = fmaf(rav[u], rbv[w], acc[u][w]);
    }
    __syncthreads();
  }
  #pragma unroll
  for (int u = 0; u < 4; u++) {
    int row = m0 + ty * 4 + u;
    *(float4*)&g_H2[row * N + j0 + tx * 4] =
        make_float4(acc[u][0], acc[u][1], acc[u][2], acc[u][3]);
  }
}

// == kF: 2-hop mask (u64) + single-pass factorized gather + radix-select ====
__global__ __launch_bounds__(256) void kF(const float* __restrict__ pas2,
                                          const float* __restrict__ pad2,
                                          const float* __restrict__ pb2,
                                          float* __restrict__ out, int wk) {
  int i = blockIdx.x, tid = threadIdx.x;
  __shared__ float v[N];
  __shared__ int vlist[N];
  __shared__ float scl[N];
  __shared__ unsigned k32[N];
  __shared__ float Ev[N];
  __shared__ float E5v[N];
  __shared__ __align__(8) unsigned mb[NW];
  __shared__ int wcnt[NW + 1];
  __shared__ int hist[256];
  __shared__ float shm[8];
  __shared__ unsigned s_pfx;
  __shared__ int s_rem;
  __shared__ float s_M;

  float as2 = pas2[0], ad2 = pad2[0], b2 = pb2[0];

  if (tid < NW) {
    unsigned w = g_B[i * NW + tid];
    if (tid == (i >> 5)) w |= 1u << (i & 31);
    mb[tid] = w;
  }
  {
    const float4* h2a = (const float4*)(g_H2 + i * N);
    const float4* c2v = (const float4*)g_c2;
    float4* vv = (float4*)v;
    for (int j = tid; j < N / 4; j += 256) {
      float4 a = h2a[j], c = c2v[j];
      vv[j] = make_float4(a.x + c.x, a.y + c.y, a.z + c.z, a.w + c.w);
    }
  }
  __syncthreads();
  // 1-hop list
  if (tid < NW) wcnt[tid] = __popc(mb[tid]);
  __syncthreads();
  if (tid == 0) {
    int s = 0;
    for (int w = 0; w < NW; w++) { int c = wcnt[w]; wcnt[w] = s; s += c; }
    wcnt[NW] = s;
  }
  __syncthreads();
  int nk = wcnt[NW];
  if (tid < NW) {
    unsigned b = mb[tid]; int o = wcnt[tid];
    while (b) { int t = __ffs(b) - 1; b &= b - 1; vlist[o++] = tid * 32 + t; }
  }
  __syncthreads();
  // 2-hop: 64-bit loads, 24 u64 words x 8 slices = 192 threads
  if (tid < 8 * (NW / 2)) {
    int sy = tid / (NW / 2), cx = tid % (NW / 2);
    const unsigned long long* B64 = (const unsigned long long*)g_B;
    unsigned long long acc = 0ull;
    for (int q = sy; q < nk; q += 8) acc |= B64[vlist[q] * (NW / 2) + cx];
    atomicOr(&mb[cx * 2], (unsigned)acc);
    atomicOr(&mb[cx * 2 + 1], (unsigned)(acc >> 32));
  }
  __syncthreads();
  // valid list (ascending index order — stable tie-break depends on it)
  if (tid < NW) wcnt[tid] = __popc(mb[tid]);
  __syncthreads();
  if (tid == 0) {
    int s = 0;
    for (int w = 0; w < NW; w++) { int c = wcnt[w]; wcnt[w] = s; s += c; }
    wcnt[NW] = s;
  }
  __syncthreads();
  int nvv = wcnt[NW];
  if (tid < NW) {
    unsigned b = mb[tid]; int o = wcnt[tid];
    while (b) { int t = __ffs(b) - 1; b &= b - 1; vlist[o++] = tid * 32 + t; }
  }
  __syncthreads();
  // row max M of as2*v[s] over valid s
  {
    float lm = -3.4e38f;
    for (int li = tid; li < nvv; li += 256)
      lm = fmaxf(lm, as2 * v[vlist[li]]);
    #pragma unroll
    for (int o = 16; o; o >>= 1) lm = fmaxf(lm, __shfl_xor_sync(0xFFFFFFFFu, lm, o));
    if ((tid & 31) == 0) shm[tid >> 5] = lm;
    __syncthreads();
    if (tid == 0) {
      float mm = shm[0];
      #pragma unroll
      for (int q = 1; q < 8; q++) mm = fmaxf(mm, shm[q]);
      s_M = mm;
    }
    __syncthreads();
  }
  float M = s_M;
  for (int li = tid; li < nvv; li += 256) {
    int s = vlist[li];
    float a = as2 * v[s] - M;
    Ev[s]  = __expf(a);
    E5v[s] = __expf(0.2f * a);
  }
  __syncthreads();
  // single-pass factorized gather softmax (offset-invariant ratio)
  for (int li = tid; li < nvv; li += 256) {
    int t = vlist[li];
    int p0 = g_offT[t], p1 = g_offT[t + 1];
    float adt = ad2 * v[t];
    float am = adt + M;
    float m = fmaxf(am, 0.f);
    float F1 = __expf(am - m);
    float F5 = __expf(0.2f * am - m);
    float den = 0.f, num = 0.f;
    for (int p = p0; p < p1; p++) {
      int s = g_srcT[p];
      if ((mb[s >> 5] >> (s & 31)) & 1u) {
        float vs = v[s];
        float u = fmaf(as2, vs, adt);
        float w = (u > 0.f) ? Ev[s] * F1 : E5v[s] * F5;
        den += w;
        num = fmaf(w, vs, num);
      }
    }
    if (den < 1e-30f) {
      float mm = -3.4e38f;
      for (int p = p0; p < p1; p++) {
        int s = g_srcT[p];
        if ((mb[s >> 5] >> (s & 31)) & 1u)
          mm = fmaxf(mm, lrelu(fmaf(as2, v[s], adt)));
      }
      den = 0.f; num = 0.f;
      for (int p = p0; p < p1; p++) {
        int s = g_srcT[p];
        if ((mb[s >> 5] >> (s & 31)) & 1u) {
          float vs = v[s];
          float w = __expf(lrelu(fmaf(as2, vs, adt)) - mm);
          den += w;
          num = fmaf(w, vs, num);
        }
      }
    }
    float sc = num / fmaxf(den, 1e-12f) + b2;
    scl[li] = sc;
    k32[li] = fenc(sc);
  }
  int kk = (nvv + 1) >> 1;
  if (tid == 0) { s_rem = kk; s_pfx = 0u; }
  __syncthreads();
  // radix-select the kk-th largest key
  for (int r = 0; r < 4; r++) {
    int shift = 24 - 8 * r;
    hist[tid] = 0;
    __syncthreads();
    unsigned pfx = s_pfx;
    for (int li = tid; li < nvv; li += 256) {
      unsigned key = k32[li];
      bool cand = (r == 0) || ((key >> (shift + 8)) == pfx);
      if (cand) atomicAdd(&hist[(key >> shift) & 255], 1);
    }
    __syncthreads();
    if (tid < 32) {
      int s = 0;
      #pragma unroll
      for (int u = 0; u < 8; u++) s += hist[tid * 8 + u];
      int cum = s;
      #pragma unroll
      for (int o = 1; o < 32; o <<= 1) {
        int t2 = __shfl_down_sync(0xFFFFFFFFu, cum, o);
        if (tid + o < 32) cum += t2;
      }
      int run = cum - s;
      int rem = s_rem;
      unsigned pfxold = s_pfx;
      int fb = -1, frem = 0;
      for (int bb = tid * 8 + 7; bb >= tid * 8; bb--) {
        int h = hist[bb];
        if (run < rem && rem <= run + h) { fb = bb; frem = rem - run; }
        run += h;
      }
      __syncwarp();
      if (fb >= 0) { s_pfx = (pfxold << 8) | (unsigned)fb; s_rem = frem; }
    }
    __syncthreads();
  }
  unsigned T = s_pfx;
  int rem = s_rem;
  for (int li = tid; li < nvv; li += 256) {
    unsigned key = k32[li];
    bool keep = key > T;
    if (!keep && key == T) {
      int cnt = 0;
      for (int l2 = 0; l2 < li; l2++) cnt += (k32[l2] == T);
      keep = cnt < rem;
    }
    if (keep) {
      int j = vlist[li];
      float sj = scl[li];
      out[i * N + j] = 1.f / (1.f + __expf(-sj));
      if (wk) out[N * N + i * N + j] = 1.f;
    }
  }
}

// ---------------- launch: forked-capture graph ----------------
extern "C" void kernel_launch(void* const* d_in, const int* in_sizes, int n_in,
                              void* d_out, int out_size) {
  const float* x   = (const float*)d_in[0];
  const float* xo  = (const float*)d_in[1];
  const int*   ei  = (const int*)d_in[2];
  const float* W1  = (const float*)d_in[4];
  const float* a1  = (const float*)d_in[5];
  const float* a2  = (const float*)d_in[6];
  const float* b1  = (const float*)d_in[7];
  const float* w2  = (const float*)d_in[8];
  const float* as2 = (const float*)d_in[9];
  const float* ad2 = (const float*)d_in[10];
  const float* b2  = (const float*)d_in[11];
  float* out = (float*)d_out;
  int wk = (out_size >= 2 * N * N) ? 1 : 0;

  cudaEventRecord(g_hs.e0, 0);
  cudaStreamWaitEvent(g_hs.s1, g_hs.e0, 0);
  cudaStreamWaitEvent(g_hs.s2, g_hs.e0, 0);
  cudaStreamWaitEvent(g_hs.s3, g_hs.e0, 0);

  // s3: zero out + g_B
  kZero<<<512, 256, 0, g_hs.s3>>>(out, out_size);
  cudaEventRecord(g_hs.e3, g_hs.s3);

  // s1: vec1 -> sada
  kVec1<<<HD + N, 256, 0, g_hs.s1>>>(W1, a1, a2, b1, w2, xo);
  kSada<<<192, 256, 0, g_hs.s1>>>(x);
  cudaEventRecord(g_hs.e1, g_hs.s1);

  // s2: U partials (WMMA) -> U reduce
  kUp<<<48 * ZU, 256, 0, g_hs.s2>>>(W1, w2, xo);
  kUred<<<(HD * N) / 256, 256, 0, g_hs.s2>>>();
  cudaEventRecord(g_hs.e2, g_hs.s2);

  // s0 (default): critical path
  kCount<<<E2 / 256, 256>>>(ei);
  kScan<<<1, 256>>>();
  cudaStreamWaitEvent(0, g_hs.e3, 0);   // g_B zeroed before fill's atomicOr
  kFill<<<E2 / 256, 256>>>(ei);
  cudaStreamWaitEvent(0, g_hs.e1, 0);   // sada done before xg
  kXg<<<N, 128>>>(x);
  cudaStreamWaitEvent(0, g_hs.e2, 0);   // U ready before H2
  kH2<<<576, 256>>>();
  kF<<<N, 256>>>(as2, ad2, b2, out, wk);
}

// round 16
// speedup vs baseline: 1.3394x; 1.0490x over previous
#include <cuda_runtime.h>
#include <cuda_bf16.h>
#include <mma.h>
#include <math.h>

using namespace nvcuda;

#define N 1536
#define EE 24576
#define E2 (EE + N)
#define HD 128
#define DD 1280
#define NW 48   // N/32 bitmask words per row
#define ZU 10   // split-K depth for U (K-chunk 128)

// ---------------- device scratch (no allocations allowed) ----------------
__device__ float g_wa[HD], g_wb[HD], g_c2[N];
__device__ float g_sa[N], g_da[N];
__device__ float g_Up[ZU * HD * N];
__device__ __align__(16) __nv_bfloat16 g_Ah[HD * DD], g_Al[HD * DD];   // (W1.*w2) split
__device__ __align__(16) __nv_bfloat16 g_Bh[N * DD],  g_Bl[N * DD];    // xo split
__device__ __align__(16) __nv_bfloat16 g_Uh[HD * N],  g_Ul[HD * N];    // U split
__device__ __align__(16) __nv_bfloat16 g_xgh[N * HD], g_xgl[N * HD];   // xg split
__device__ float g_H2[N * N];
__device__ int   g_cntT[N], g_offT[N + 1], g_curT[N];
__device__ int   g_cntS[N], g_offS[N + 1], g_curS[N];
__device__ int   g_srcT[E2];
__device__ int   g_tgtS[EE];
__device__ __align__(16) unsigned g_B[N * NW];

__device__ __forceinline__ float lrelu(float v) { return v > 0.f ? v : 0.2f * v; }
__device__ __forceinline__ unsigned fenc(float f) {
  unsigned u = __float_as_uint(f);
  return (u & 0x80000000u) ? ~u : (u | 0x80000000u);
}

__device__ __forceinline__ float blockSum256(float v, float* sh) {
  __syncthreads();
  #pragma unroll
  for (int o = 16; o; o >>= 1) v += __shfl_xor_sync(0xFFFFFFFFu, v, o);
  if ((threadIdx.x & 31) == 0) sh[threadIdx.x >> 5] = v;
  __syncthreads();
  if (threadIdx.x < 32) {
    v = (threadIdx.x < 8) ? sh[threadIdx.x] : 0.f;
    #pragma unroll
    for (int o = 4; o; o >>= 1) v += __shfl_xor_sync(0xFFFFFFFFu, v, o);
  }
  return v;
}

// ---------- host-side fork/join resources ----------
struct HxStreams {
  cudaStream_t s1, s2, s3;
  cudaEvent_t e0, e1, e2, e3;
  HxStreams() {
    cudaStreamCreateWithFlags(&s1, cudaStreamNonBlocking);
    cudaStreamCreateWithFlags(&s2, cudaStreamNonBlocking);
    cudaStreamCreateWithFlags(&s3, cudaStreamNonBlocking);
    cudaEventCreateWithFlags(&e0, cudaEventDisableTiming);
    cudaEventCreateWithFlags(&e1, cudaEventDisableTiming);
    cudaEventCreateWithFlags(&e2, cudaEventDisableTiming);
    cudaEventCreateWithFlags(&e3, cudaEventDisableTiming);
  }
};
static HxStreams g_hs;

// ============ kZero: zero out buffer + g_B ===============
__global__ void kZero(float* __restrict__ out, int out_size) {
  int i = blockIdx.x * blockDim.x + threadIdx.x;
  int stride = gridDim.x * blockDim.x;
  for (int p = i; p < out_size; p += stride) out[p] = 0.f;
  for (int p = i; p < N * NW; p += stride) g_B[p] = 0u;
}

// ============ kSplit: one-time bf16 hi/lo split of A=(W1.*w2) and B=xo =====
__global__ void kSplit(const float* __restrict__ W1, const float* __restrict__ w2,
                       const float* __restrict__ xo) {
  int idx = blockIdx.x * blockDim.x + threadIdx.x;
  int stride = gridDim.x * blockDim.x;
  for (int p = idx; p < HD * DD + N * DD; p += stride) {
    if (p < HD * DD) {
      float a = W1[p] * w2[p % DD];
      __nv_bfloat16 h = __float2bfloat16(a);
      g_Ah[p] = h;
      g_Al[p] = __float2bfloat16(a - __bfloat162float(h));
    } else {
      int q = p - HD * DD;
      float b = xo[q];
      __nv_bfloat16 h = __float2bfloat16(b);
      g_Bh[q] = h;
      g_Bl[q] = __float2bfloat16(b - __bfloat162float(h));
    }
  }
}

// ============ kCount ===================================
__global__ void kCount(const int* __restrict__ ei) {
  int idx = blockIdx.x * blockDim.x + threadIdx.x;
  if (idx < EE) {
    atomicAdd(&g_cntS[ei[idx]], 1);
    atomicAdd(&g_cntT[ei[EE + idx]], 1);
  } else if (idx < E2) {
    atomicAdd(&g_cntT[idx - EE], 1);
  }
}

// ============ kScan ========================
__global__ void kScan() {
  __shared__ int part[256];
  int tid = threadIdx.x;
  int base = tid * 6;
  {
    int a[6]; int s = 0;
    #pragma unroll
    for (int u = 0; u < 6; u++) { a[u] = g_cntT[base + u]; s += a[u]; }
    part[tid] = s;
    __syncthreads();
    for (int o = 1; o < 256; o <<= 1) {
      int v = (tid >= o) ? part[tid - o] : 0;
      __syncthreads();
      part[tid] += v;
      __syncthreads();
    }
    int excl = part[tid] - s;
    #pragma unroll
    for (int u = 0; u < 6; u++) {
      g_offT[base + u] = excl; g_curT[base + u] = excl; excl += a[u];
    }
    if (tid == 255) g_offT[N] = part[255];
    __syncthreads();
  }
  {
    int a[6]; int s = 0;
    #pragma unroll
    for (int u = 0; u < 6; u++) { a[u] = g_cntS[base + u]; s += a[u]; }
    part[tid] = s;
    __syncthreads();
    for (int o = 1; o < 256; o <<= 1) {
      int v = (tid >= o) ? part[tid - o] : 0;
      __syncthreads();
      part[tid] += v;
      __syncthreads();
    }
    int excl = part[tid] - s;
    #pragma unroll
    for (int u = 0; u < 6; u++) {
      g_offS[base + u] = excl; g_curS[base + u] = excl; excl += a[u];
    }
    if (tid == 255) g_offS[N] = part[255];
  }
}

// ============ kFill: CSR fill + B build + cnt re-zero ======================
__global__ void kFill(const int* __restrict__ ei) {
  int idx = blockIdx.x * blockDim.x + threadIdx.x;
  if (idx < N) { g_cntT[idx] = 0; g_cntS[idx] = 0; }
  if (idx >= E2) return;
  int s, t;
  if (idx < EE) { s = ei[idx]; t = ei[EE + idx]; }
  else { s = t = idx - EE; }
  int pos = atomicAdd(&g_curT[t], 1);
  g_srcT[pos] = s;
  if (idx < EE) {
    int ps = atomicAdd(&g_curS[s], 1);
    g_tgtS[ps] = t;
    atomicOr(&g_B[t * NW + (s >> 5)], 1u << (s & 31));
  }
}

// ============ kVec1 ============================
__global__ __launch_bounds__(256) void kVec1(const float* __restrict__ W1,
                                             const float* __restrict__ a1,
                                             const float* __restrict__ a2,
                                             const float* __restrict__ b1,
                                             const float* __restrict__ w2,
                                             const float* __restrict__ xo) {
  __shared__ float sh[8];
  int b = blockIdx.x, tid = threadIdx.x;
  if (b < HD) {
    float s1 = 0.f, s2 = 0.f;
    for (int d = tid; d < DD; d += 256) {
      float w = W1[b * DD + d];
      s1 += w * a1[d]; s2 += w * a2[d];
    }
    float r1 = blockSum256(s1, sh);
    float r2 = blockSum256(s2, sh);
    if (tid == 0) { g_wa[b] = r1; g_wb[b] = r2; }
  } else {
    int j = b - HD;
    float s = 0.f;
    for (int d = tid; d < DD; d += 256) s += b1[d] * w2[d] * xo[j * DD + d];
    float r = blockSum256(s, sh);
    if (tid == 0) g_c2[j] = r;
  }
}

// ============ kSada ==================================
__global__ __launch_bounds__(256) void kSada(const float* __restrict__ x) {
  int node = blockIdx.x * 8 + (threadIdx.x >> 5);
  int lane = threadIdx.x & 31;
  if (node >= N) return;
  float s1 = 0.f, s2 = 0.f;
  #pragma unroll
  for (int k = lane; k < HD; k += 32) {
    float xv = x[node * HD + k];
    s1 += xv * g_wa[k]; s2 += xv * g_wb[k];
  }
  #pragma unroll
  for (int o = 16; o; o >>= 1) {
    s1 += __shfl_xor_sync(0xFFFFFFFFu, s1, o);
    s2 += __shfl_xor_sync(0xFFFFFFFFu, s2, o);
  }
  if (lane == 0) { g_sa[node] = s1; g_da[node] = s2; }
}

// == kUp: U split-K partials via WMMA; bf16 operands pre-split in global ====
__global__ __launch_bounds__(256, 2) void kUp() {
  __shared__ __align__(16) __nv_bfloat16 Ah[64][72];
  __shared__ __align__(16) __nv_bfloat16 Al[64][72];
  __shared__ __align__(16) __nv_bfloat16 Bh[64][72];
  __shared__ __align__(16) __nv_bfloat16 Bl[64][72];
  int b = blockIdx.x;
  int tileid = b % 48;          // 24 j-tiles x 2 m-tiles
  int z = b / 48;
  int j0 = (tileid % 24) * 64;
  int m0 = (tileid / 24) * 64;
  int k0 = z * 128;
  int tid = threadIdx.x;
  int wid = tid >> 5;
  int wm = wid >> 1;
  int wn = wid & 1;

  wmma::fragment<wmma::accumulator, 16, 16, 16, float> acc[2];
  wmma::fill_fragment(acc[0], 0.f);
  wmma::fill_fragment(acc[1], 0.f);

  for (int kc = 0; kc < 128; kc += 64) {
    for (int l = tid; l < 64 * 8; l += 256) {   // uint4 = 8 bf16
      int r = l >> 3, k = (l & 7) * 8;
      *(uint4*)&Ah[r][k] = *(const uint4*)&g_Ah[(m0 + r) * DD + k0 + kc + k];
      *(uint4*)&Al[r][k] = *(const uint4*)&g_Al[(m0 + r) * DD + k0 + kc + k];
      *(uint4*)&Bh[r][k] = *(const uint4*)&g_Bh[(j0 + r) * DD + k0 + kc + k];
      *(uint4*)&Bl[r][k] = *(const uint4*)&g_Bl[(j0 + r) * DD + k0 + kc + k];
    }
    __syncthreads();
    #pragma unroll
    for (int kk = 0; kk < 64; kk += 16) {
      wmma::fragment<wmma::matrix_a, 16, 16, 16, __nv_bfloat16, wmma::row_major> ah, al;
      wmma::load_matrix_sync(ah, &Ah[wm * 16][kk], 72);
      wmma::load_matrix_sync(al, &Al[wm * 16][kk], 72);
      #pragma unroll
      for (int t = 0; t < 2; t++) {
        int n = wn * 32 + t * 16;
        wmma::fragment<wmma::matrix_b, 16, 16, 16, __nv_bfloat16, wmma::col_major> bh, bl;
        wmma::load_matrix_sync(bh, &Bh[n][kk], 72);
        wmma::load_matrix_sync(bl, &Bl[n][kk], 72);
        wmma::mma_sync(acc[t], ah, bh, acc[t]);
        wmma::mma_sync(acc[t], ah, bl, acc[t]);
        wmma::mma_sync(acc[t], al, bh, acc[t]);
      }
    }
    __syncthreads();
  }
  float* Up = g_Up + z * (HD * N);
  #pragma unroll
  for (int t = 0; t < 2; t++)
    wmma::store_matrix_sync(&Up[(m0 + wm * 16) * N + j0 + wn * 32 + t * 16],
                            acc[t], N, wmma::mem_row_major);
}

// ============ kUred: reduce partials + emit U bf16 split ===================
__global__ void kUred() {
  int idx = blockIdx.x * blockDim.x + threadIdx.x;
  float s = 0.f;
  #pragma unroll
  for (int z = 0; z < ZU; z++) s += g_Up[z * (HD * N) + idx];
  __nv_bfloat16 h = __float2bfloat16(s);
  g_Uh[idx] = h;
  g_Ul[idx] = __float2bfloat16(s - __bfloat162float(h));
}

// ========= kXg: fused GAT-1 softmax + xg = P@x, emit bf16 split ============
__global__ __launch_bounds__(128) void kXg(const float* __restrict__ x) {
  int t = blockIdx.x, tid = threadIdx.x;
  __shared__ int   ss[256];
  __shared__ float sw[256];
  __shared__ float sh[4];
  int p0 = g_offT[t], p1 = g_offT[t + 1];
  float dt = g_da[t];
  float m = -3.4e38f;
  for (int p = p0 + tid; p < p1; p += 128)
    m = fmaxf(m, lrelu(g_sa[g_srcT[p]] + dt));
  #pragma unroll
  for (int o = 16; o; o >>= 1) m = fmaxf(m, __shfl_xor_sync(0xFFFFFFFFu, m, o));
  if ((tid & 31) == 0) sh[tid >> 5] = m;
  __syncthreads();
  m = fmaxf(fmaxf(sh[0], sh[1]), fmaxf(sh[2], sh[3]));
  float acc = 0.f, dsum = 0.f;
  for (int base = p0; base < p1; base += 256) {
    int nc = min(256, p1 - base);
    for (int q = tid; q < nc; q += 128) {
      int s = g_srcT[base + q];
      float w = expf(lrelu(g_sa[s] + dt) - m);
      ss[q] = s;
      sw[q] = w;
      dsum += w;
    }
    __syncthreads();
    for (int q = 0; q < nc; q++)
      acc += sw[q] * x[ss[q] * HD + tid];
    __syncthreads();
  }
  float den = dsum;
  #pragma unroll
  for (int o = 16; o; o >>= 1) den += __shfl_xor_sync(0xFFFFFFFFu, den, o);
  if ((tid & 31) == 0) sh[tid >> 5] = den;
  __syncthreads();
  den = sh[0] + sh[1] + sh[2] + sh[3];
  float xv = acc / den;
  __nv_bfloat16 h = __float2bfloat16(xv);
  g_xgh[t * HD + tid] = h;
  g_xgl[t * HD + tid] = __float2bfloat16(xv - __bfloat162float(h));
}

// == kH2: H2 = xg @ U via WMMA 3-term split; 64x64 tiles ====================
__global__ __launch_bounds__(256, 2) void kH2() {
  __shared__ __align__(16) __nv_bfloat16 Ah[64][72];
  __shared__ __align__(16) __nv_bfloat16 Al[64][72];
  __shared__ __align__(16) __nv_bfloat16 Bh[64][72];
  __shared__ __align__(16) __nv_bfloat16 Bl[64][72];
  int b = blockIdx.x;
  int j0 = (b % 24) * 64;
  int m0 = (b / 24) * 64;
  int tid = threadIdx.x;
  int wid = tid >> 5;
  int wm = wid >> 1;
  int wn = wid & 1;

  wmma::fragment<wmma::accumulator, 16, 16, 16, float> acc[2];
  wmma::fill_fragment(acc[0], 0.f);
  wmma::fill_fragment(acc[1], 0.f);

  for (int kc = 0; kc < HD; kc += 64) {
    for (int l = tid; l < 64 * 8; l += 256) {
      int r = l >> 3, k = (l & 7) * 8;
      *(uint4*)&Ah[r][k] = *(const uint4*)&g_xgh[(m0 + r) * HD + kc + k];
      *(uint4*)&Al[r][k] = *(const uint4*)&g_xgl[(m0 + r) * HD + kc + k];
      // B: U[k][j] row-major -> smem [k][j] tile (r indexes k here)
      *(uint4*)&Bh[r][k] = *(const uint4*)&g_Uh[(kc + r) * N + j0 + k];
      *(uint4*)&Bl[r][k] = *(const uint4*)&g_Ul[(kc + r) * N + j0 + k];
    }
    __syncthreads();
    #pragma unroll
    for (int kk = 0; kk < 64; kk += 16) {
      wmma::fragment<wmma::matrix_a, 16, 16, 16, __nv_bfloat16, wmma::row_major> ah, al;
      wmma::load_matrix_sync(ah, &Ah[wm * 16][kk], 72);
      wmma::load_matrix_sync(al, &Al[wm * 16][kk], 72);
      #pragma unroll
      for (int t = 0; t < 2; t++) {
        int n = wn * 32 + t * 16;
        wmma::fragment<wmma::matrix_b, 16, 16, 16, __nv_bfloat16, wmma::row_major> bh, bl;
        wmma::load_matrix_sync(bh, &Bh[kk][n], 72);
        wmma::load_matrix_sync(bl, &Bl[kk][n], 72);
        wmma::mma_sync(acc[t], ah, bh, acc[t]);
        wmma::mma_sync(acc[t], ah, bl, acc[t]);
        wmma::mma_sync(acc[t], al, bh, acc[t]);
      }
    }
    __syncthreads();
  }
  #pragma unroll
  for (int t = 0; t < 2; t++)
    wmma::store_matrix_sync(&g_H2[(m0 + wm * 16) * N + j0 + wn * 32 + t * 16],
                            acc[t], N, wmma::mem_row_major);
}

// == kF: 2-hop mask (u64) + single-pass factorized gather + radix-select ====
__global__ __launch_bounds__(256) void kF(const float* __restrict__ pas2,
                                          const float* __restrict__ pad2,
                                          const float* __restrict__ pb2,
                                          float* __restrict__ out, int wk) {
  int i = blockIdx.x, tid = threadIdx.x;
  __shared__ float v[N];
  __shared__ int vlist[N];
  __shared__ float scl[N];
  __shared__ unsigned k32[N];
  __shared__ float Ev[N];
  __shared__ float E5v[N];
  __shared__ __align__(8) unsigned mb[NW];
  __shared__ int wcnt[NW + 1];
  __shared__ int hist[256];
  __shared__ float shm[8];
  __shared__ unsigned s_pfx;
  __shared__ int s_rem;
  __shared__ float s_M;

  float as2 = pas2[0], ad2 = pad2[0], b2 = pb2[0];

  if (tid < NW) {
    unsigned w = g_B[i * NW + tid];
    if (tid == (i >> 5)) w |= 1u << (i & 31);
    mb[tid] = w;
  }
  {
    const float4* h2a = (const float4*)(g_H2 + i * N);
    const float4* c2v = (const float4*)g_c2;
    float4* vv = (float4*)v;
    for (int j = tid; j < N / 4; j += 256) {
      float4 a = h2a[j], c = c2v[j];
      vv[j] = make_float4(a.x + c.x, a.y + c.y, a.z + c.z, a.w + c.w);
    }
  }
  __syncthreads();
  if (tid < NW) wcnt[tid] = __popc(mb[tid]);
  __syncthreads();
  if (tid == 0) {
    int s = 0;
    for (int w = 0; w < NW; w++) { int c = wcnt[w]; wcnt[w] = s; s += c; }
    wcnt[NW] = s;
  }
  __syncthreads();
  int nk = wcnt[NW];
  if (tid < NW) {
    unsigned b = mb[tid]; int o = wcnt[tid];
    while (b) { int t = __ffs(b) - 1; b &= b - 1; vlist[o++] = tid * 32 + t; }
  }
  __syncthreads();
  if (tid < 8 * (NW / 2)) {
    int sy = tid / (NW / 2), cx = tid % (NW / 2);
    const unsigned long long* B64 = (const unsigned long long*)g_B;
    unsigned long long acc = 0ull;
    for (int q = sy; q < nk; q += 8) acc |= B64[vlist[q] * (NW / 2) + cx];
    atomicOr(&mb[cx * 2], (unsigned)acc);
    atomicOr(&mb[cx * 2 + 1], (unsigned)(acc >> 32));
  }
  __syncthreads();
  if (tid < NW) wcnt[tid] = __popc(mb[tid]);
  __syncthreads();
  if (tid == 0) {
    int s = 0;
    for (int w = 0; w < NW; w++) { int c = wcnt[w]; wcnt[w] = s; s += c; }
    wcnt[NW] = s;
  }
  __syncthreads();
  int nvv = wcnt[NW];
  if (tid < NW) {
    unsigned b = mb[tid]; int o = wcnt[tid];
    while (b) { int t = __ffs(b) - 1; b &= b - 1; vlist[o++] = tid * 32 + t; }
  }
  __syncthreads();
  {
    float lm = -3.4e38f;
    for (int li = tid; li < nvv; li += 256)
      lm = fmaxf(lm, as2 * v[vlist[li]]);
    #pragma unroll
    for (int o = 16; o; o >>= 1) lm = fmaxf(lm, __shfl_xor_sync(0xFFFFFFFFu, lm, o));
    if ((tid & 31) == 0) shm[tid >> 5] = lm;
    __syncthreads();
    if (tid == 0) {
      float mm = shm[0];
      #pragma unroll
      for (int q = 1; q < 8; q++) mm = fmaxf(mm, shm[q]);
      s_M = mm;
    }
    __syncthreads();
  }
  float M = s_M;
  for (int li = tid; li < nvv; li += 256) {
    int s = vlist[li];
    float a = as2 * v[s] - M;
    Ev[s]  = __expf(a);
    E5v[s] = __expf(0.2f * a);
  }
  __syncthreads();
  for (int li = tid; li < nvv; li += 256) {
    int t = vlist[li];
    int p0 = g_offT[t], p1 = g_offT[t + 1];
    float adt = ad2 * v[t];
    float am = adt + M;
    float m = fmaxf(am, 0.f);
    float F1 = __expf(am - m);
    float F5 = __expf(0.2f * am - m);
    float den = 0.f, num = 0.f;
    for (int p = p0; p < p1; p++) {
      int s = g_srcT[p];
      if ((mb[s >> 5] >> (s & 31)) & 1u) {
        float vs = v[s];
        float u = fmaf(as2, vs, adt);
        float w = (u > 0.f) ? Ev[s] * F1 : E5v[s] * F5;
        den += w;
        num = fmaf(w, vs, num);
      }
    }
    if (den < 1e-30f) {
      float mm = -3.4e38f;
      for (int p = p0; p < p1; p++) {
        int s = g_srcT[p];
        if ((mb[s >> 5] >> (s & 31)) & 1u)
          mm = fmaxf(mm, lrelu(fmaf(as2, v[s], adt)));
      }
      den = 0.f; num = 0.f;
      for (int p = p0; p < p1; p++) {
        int s = g_srcT[p];
        if ((mb[s >> 5] >> (s & 31)) & 1u) {
          float vs = v[s];
          float w = __expf(lrelu(fmaf(as2, vs, adt)) - mm);
          den += w;
          num = fmaf(w, vs, num);
        }
      }
    }
    float sc = num / fmaxf(den, 1e-12f) + b2;
    scl[li] = sc;
    k32[li] = fenc(sc);
  }
  int kk = (nvv + 1) >> 1;
  if (tid == 0) { s_rem = kk; s_pfx = 0u; }
  __syncthreads();
  for (int r = 0; r < 4; r++) {
    int shift = 24 - 8 * r;
    hist[tid] = 0;
    __syncthreads();
    unsigned pfx = s_pfx;
    for (int li = tid; li < nvv; li += 256) {
      unsigned key = k32[li];
      bool cand = (r == 0) || ((key >> (shift + 8)) == pfx);
      if (cand) atomicAdd(&hist[(key >> shift) & 255], 1);
    }
    __syncthreads();
    if (tid < 32) {
      int s = 0;
      #pragma unroll
      for (int u = 0; u < 8; u++) s += hist[tid * 8 + u];
      int cum = s;
      #pragma unroll
      for (int o = 1; o < 32; o <<= 1) {
        int t2 = __shfl_down_sync(0xFFFFFFFFu, cum, o);
        if (tid + o < 32) cum += t2;
      }
      int run = cum - s;
      int rem = s_rem;
      unsigned pfxold = s_pfx;
      int fb = -1, frem = 0;
      for (int bb = tid * 8 + 7; bb >= tid * 8; bb--) {
        int h = hist[bb];
        if (run < rem && rem <= run + h) { fb = bb; frem = rem - run; }
        run += h;
      }
      __syncwarp();
      if (fb >= 0) { s_pfx = (pfxold << 8) | (unsigned)fb; s_rem = frem; }
    }
    __syncthreads();
  }
  unsigned T = s_pfx;
  int rem = s_rem;
  for (int li = tid; li < nvv; li += 256) {
    unsigned key = k32[li];
    bool keep = key > T;
    if (!keep && key == T) {
      int cnt = 0;
      for (int l2 = 0; l2 < li; l2++) cnt += (k32[l2] == T);
      keep = cnt < rem;
    }
    if (keep) {
      int j = vlist[li];
      float sj = scl[li];
      out[i * N + j] = 1.f / (1.f + __expf(-sj));
      if (wk) out[N * N + i * N + j] = 1.f;
    }
  }
}

// ---------------- launch: forked-capture graph ----------------
extern "C" void kernel_launch(void* const* d_in, const int* in_sizes, int n_in,
                              void* d_out, int out_size) {
  const float* x   = (const float*)d_in[0];
  const float* xo  = (const float*)d_in[1];
  const int*   ei  = (const int*)d_in[2];
  const float* W1  = (const float*)d_in[4];
  const float* a1  = (const float*)d_in[5];
  const float* a2  = (const float*)d_in[6];
  const float* b1  = (const float*)d_in[7];
  const float* w2  = (const float*)d_in[8];
  const float* as2 = (const float*)d_in[9];
  const float* ad2 = (const float*)d_in[10];
  const float* b2  = (const float*)d_in[11];
  float* out = (float*)d_out;
  int wk = (out_size >= 2 * N * N) ? 1 : 0;

  cudaEventRecord(g_hs.e0, 0);
  cudaStreamWaitEvent(g_hs.s1, g_hs.e0, 0);
  cudaStreamWaitEvent(g_hs.s2, g_hs.e0, 0);
  cudaStreamWaitEvent(g_hs.s3, g_hs.e0, 0);

  // s3: zero out + g_B
  kZero<<<512, 256, 0, g_hs.s3>>>(out, out_size);
  cudaEventRecord(g_hs.e3, g_hs.s3);

  // s1: vec1 -> sada
  kVec1<<<HD + N, 256, 0, g_hs.s1>>>(W1, a1, a2, b1, w2, xo);
  kSada<<<192, 256, 0, g_hs.s1>>>(x);
  cudaEventRecord(g_hs.e1, g_hs.s1);

  // s2: split -> U partials (WMMA) -> U reduce+split
  kSplit<<<592, 256, 0, g_hs.s2>>>(W1, w2, xo);
  kUp<<<48 * ZU, 256, 0, g_hs.s2>>>();
  kUred<<<(HD * N) / 256, 256, 0, g_hs.s2>>>();
  cudaEventRecord(g_hs.e2, g_hs.s2);

  // s0 (default): critical path
  kCount<<<E2 / 256, 256>>>(ei);
  kScan<<<1, 256>>>();
  cudaStreamWaitEvent(0, g_hs.e3, 0);   // g_B zeroed before fill's atomicOr
  kFill<<<E2 / 256, 256>>>(ei);
  cudaStreamWaitEvent(0, g_hs.e1, 0);   // sada done before xg
  kXg<<<N, 128>>>(x);
  cudaStreamWaitEvent(0, g_hs.e2, 0);   // U ready before H2
  kH2<<<576, 256>>>();
  kF<<<N, 256>>>(as2, ad2, b2, out, wk);
}

// round 17
// speedup vs baseline: 1.3775x; 1.0285x over previous
#include <cuda_runtime.h>
#include <cuda_bf16.h>
#include <mma.h>
#include <math.h>

using namespace nvcuda;

#define N 1536
#define EE 24576
#define E2 (EE + N)
#define HD 128
#define DD 1280
#define NW 48   // N/32 bitmask words per row
#define ZU 10   // split-K depth for U (K-chunk 128)

// ---------------- device scratch (no allocations allowed) ----------------
__device__ float g_wa[HD], g_wb[HD], g_c2[N];
__device__ float g_sa[N], g_da[N];
__device__ float g_Up[ZU * HD * N];
__device__ __align__(16) __nv_bfloat16 g_Ah[HD * DD], g_Al[HD * DD];   // (W1.*w2) split
__device__ __align__(16) __nv_bfloat16 g_Bh[N * DD],  g_Bl[N * DD];    // xo split
__device__ __align__(16) __nv_bfloat16 g_Uh[HD * N],  g_Ul[HD * N];    // U split
__device__ __align__(16) __nv_bfloat16 g_xgh[N * HD], g_xgl[N * HD];   // xg split
__device__ float g_H2[N * N];
__device__ int   g_cntT[N], g_offT[N + 1], g_curT[N];
__device__ int   g_cntS[N], g_offS[N + 1], g_curS[N];
__device__ int   g_srcT[E2];
__device__ int   g_tgtS[EE];
__device__ __align__(16) unsigned g_B[N * NW];

__device__ __forceinline__ float lrelu(float v) { return v > 0.f ? v : 0.2f * v; }
__device__ __forceinline__ unsigned fenc(float f) {
  unsigned u = __float_as_uint(f);
  return (u & 0x80000000u) ? ~u : (u | 0x80000000u);
}

__device__ __forceinline__ float blockSum256(float v, float* sh) {
  __syncthreads();
  #pragma unroll
  for (int o = 16; o; o >>= 1) v += __shfl_xor_sync(0xFFFFFFFFu, v, o);
  if ((threadIdx.x & 31) == 0) sh[threadIdx.x >> 5] = v;
  __syncthreads();
  if (threadIdx.x < 32) {
    v = (threadIdx.x < 8) ? sh[threadIdx.x] : 0.f;
    #pragma unroll
    for (int o = 4; o; o >>= 1) v += __shfl_xor_sync(0xFFFFFFFFu, v, o);
  }
  return v;
}

// pack 2 floats -> bf16x2 (hi parts) and residual bf16x2 (lo parts)
__device__ __forceinline__ void split2(float a, float b, unsigned& hi, unsigned& lo) {
  __nv_bfloat162 h = __floats2bfloat162_rn(a, b);  // per-lane rn conversion
  float2 hf = __bfloat1622float2(h);
  __nv_bfloat162 l = __floats2bfloat162_rn(a - hf.x, b - hf.y);
  hi = *(unsigned*)&h;
  lo = *(unsigned*)&l;
}

// ---------- host-side fork/join resources ----------
struct HxStreams {
  cudaStream_t s1, s2, s3;
  cudaEvent_t e0, e1, e2, e3;
  HxStreams() {
    cudaStreamCreateWithFlags(&s1, cudaStreamNonBlocking);
    cudaStreamCreateWithFlags(&s2, cudaStreamNonBlocking);
    cudaStreamCreateWithFlags(&s3, cudaStreamNonBlocking);
    cudaEventCreateWithFlags(&e0, cudaEventDisableTiming);
    cudaEventCreateWithFlags(&e1, cudaEventDisableTiming);
    cudaEventCreateWithFlags(&e2, cudaEventDisableTiming);
    cudaEventCreateWithFlags(&e3, cudaEventDisableTiming);
  }
};
static HxStreams g_hs;

// ============ kZero: zero out buffer + g_B ===============
__global__ void kZero(float* __restrict__ out, int out_size) {
  int i = blockIdx.x * blockDim.x + threadIdx.x;
  int stride = gridDim.x * blockDim.x;
  for (int p = i; p < out_size; p += stride) out[p] = 0.f;
  for (int p = i; p < N * NW; p += stride) g_B[p] = 0u;
}

// ====== kSplit: vectorized bf16 hi/lo split of A=(W1.*w2) and B=xo =========
// One thread = one float4 (4 elements). A range: HD*DD/4 groups, then B range.
#define NA4 (HD * DD / 4)
#define NB4 (N * DD / 4)
__global__ __launch_bounds__(256) void kSplit(const float* __restrict__ W1,
                                              const float* __restrict__ w2,
                                              const float* __restrict__ xo) {
  int idx = blockIdx.x * blockDim.x + threadIdx.x;
  int stride = gridDim.x * blockDim.x;
  for (int g = idx; g < NA4 + NB4; g += stride) {
    if (g < NA4) {
      float4 a = ((const float4*)W1)[g];
      float4 w = ((const float4*)w2)[g % (DD / 4)];
      a.x *= w.x; a.y *= w.y; a.z *= w.z; a.w *= w.w;
      uint2 hi, lo;
      split2(a.x, a.y, hi.x, lo.x);
      split2(a.z, a.w, hi.y, lo.y);
      ((uint2*)g_Ah)[g] = hi;
      ((uint2*)g_Al)[g] = lo;
    } else {
      int q = g - NA4;
      float4 b = ((const float4*)xo)[q];
      uint2 hi, lo;
      split2(b.x, b.y, hi.x, lo.x);
      split2(b.z, b.w, hi.y, lo.y);
      ((uint2*)g_Bh)[q] = hi;
      ((uint2*)g_Bl)[q] = lo;
    }
  }
}

// ============ kCount ===================================
__global__ void kCount(const int* __restrict__ ei) {
  int idx = blockIdx.x * blockDim.x + threadIdx.x;
  if (idx < EE) {
    atomicAdd(&g_cntS[ei[idx]], 1);
    atomicAdd(&g_cntT[ei[EE + idx]], 1);
  } else if (idx < E2) {
    atomicAdd(&g_cntT[idx - EE], 1);
  }
}

// ============ kScan ========================
__global__ void kScan() {
  __shared__ int part[256];
  int tid = threadIdx.x;
  int base = tid * 6;
  {
    int a[6]; int s = 0;
    #pragma unroll
    for (int u = 0; u < 6; u++) { a[u] = g_cntT[base + u]; s += a[u]; }
    part[tid] = s;
    __syncthreads();
    for (int o = 1; o < 256; o <<= 1) {
      int v = (tid >= o) ? part[tid - o] : 0;
      __syncthreads();
      part[tid] += v;
      __syncthreads();
    }
    int excl = part[tid] - s;
    #pragma unroll
    for (int u = 0; u < 6; u++) {
      g_offT[base + u] = excl; g_curT[base + u] = excl; excl += a[u];
    }
    if (tid == 255) g_offT[N] = part[255];
    __syncthreads();
  }
  {
    int a[6]; int s = 0;
    #pragma unroll
    for (int u = 0; u < 6; u++) { a[u] = g_cntS[base + u]; s += a[u]; }
    part[tid] = s;
    __syncthreads();
    for (int o = 1; o < 256; o <<= 1) {
      int v = (tid >= o) ? part[tid - o] : 0;
      __syncthreads();
      part[tid] += v;
      __syncthreads();
    }
    int excl = part[tid] - s;
    #pragma unroll
    for (int u = 0; u < 6; u++) {
      g_offS[base + u] = excl; g_curS[base + u] = excl; excl += a[u];
    }
    if (tid == 255) g_offS[N] = part[255];
  }
}

// ============ kFill: CSR fill + B build + cnt re-zero ======================
__global__ void kFill(const int* __restrict__ ei) {
  int idx = blockIdx.x * blockDim.x + threadIdx.x;
  if (idx < N) { g_cntT[idx] = 0; g_cntS[idx] = 0; }
  if (idx >= E2) return;
  int s, t;
  if (idx < EE) { s = ei[idx]; t = ei[EE + idx]; }
  else { s = t = idx - EE; }
  int pos = atomicAdd(&g_curT[t], 1);
  g_srcT[pos] = s;
  if (idx < EE) {
    int ps = atomicAdd(&g_curS[s], 1);
    g_tgtS[ps] = t;
    atomicOr(&g_B[t * NW + (s >> 5)], 1u << (s & 31));
  }
}

// ============ kVec1 ============================
__global__ __launch_bounds__(256) void kVec1(const float* __restrict__ W1,
                                             const float* __restrict__ a1,
                                             const float* __restrict__ a2,
                                             const float* __restrict__ b1,
                                             const float* __restrict__ w2,
                                             const float* __restrict__ xo) {
  __shared__ float sh[8];
  int b = blockIdx.x, tid = threadIdx.x;
  if (b < HD) {
    float s1 = 0.f, s2 = 0.f;
    for (int d = tid; d < DD; d += 256) {
      float w = W1[b * DD + d];
      s1 += w * a1[d]; s2 += w * a2[d];
    }
    float r1 = blockSum256(s1, sh);
    float r2 = blockSum256(s2, sh);
    if (tid == 0) { g_wa[b] = r1; g_wb[b] = r2; }
  } else {
    int j = b - HD;
    float s = 0.f;
    for (int d = tid; d < DD; d += 256) s += b1[d] * w2[d] * xo[j * DD + d];
    float r = blockSum256(s, sh);
    if (tid == 0) g_c2[j] = r;
  }
}

// ============ kSada ==================================
__global__ __launch_bounds__(256) void kSada(const float* __restrict__ x) {
  int node = blockIdx.x * 8 + (threadIdx.x >> 5);
  int lane = threadIdx.x & 31;
  if (node >= N) return;
  float s1 = 0.f, s2 = 0.f;
  #pragma unroll
  for (int k = lane; k < HD; k += 32) {
    float xv = x[node * HD + k];
    s1 += xv * g_wa[k]; s2 += xv * g_wb[k];
  }
  #pragma unroll
  for (int o = 16; o; o >>= 1) {
    s1 += __shfl_xor_sync(0xFFFFFFFFu, s1, o);
    s2 += __shfl_xor_sync(0xFFFFFFFFu, s2, o);
  }
  if (lane == 0) { g_sa[node] = s1; g_da[node] = s2; }
}

// == kUp: U split-K partials via WMMA; bf16 operands pre-split in global ====
__global__ __launch_bounds__(256, 2) void kUp() {
  __shared__ __align__(16) __nv_bfloat16 Ah[64][72];
  __shared__ __align__(16) __nv_bfloat16 Al[64][72];
  __shared__ __align__(16) __nv_bfloat16 Bh[64][72];
  __shared__ __align__(16) __nv_bfloat16 Bl[64][72];
  int b = blockIdx.x;
  int tileid = b % 48;          // 24 j-tiles x 2 m-tiles
  int z = b / 48;
  int j0 = (tileid % 24) * 64;
  int m0 = (tileid / 24) * 64;
  int k0 = z * 128;
  int tid = threadIdx.x;
  int wid = tid >> 5;
  int wm = wid >> 1;
  int wn = wid & 1;

  wmma::fragment<wmma::accumulator, 16, 16, 16, float> acc[2];
  wmma::fill_fragment(acc[0], 0.f);
  wmma::fill_fragment(acc[1], 0.f);

  for (int kc = 0; kc < 128; kc += 64) {
    for (int l = tid; l < 64 * 8; l += 256) {   // uint4 = 8 bf16
      int r = l >> 3, k = (l & 7) * 8;
      *(uint4*)&Ah[r][k] = *(const uint4*)&g_Ah[(m0 + r) * DD + k0 + kc + k];
      *(uint4*)&Al[r][k] = *(const uint4*)&g_Al[(m0 + r) * DD + k0 + kc + k];
      *(uint4*)&Bh[r][k] = *(const uint4*)&g_Bh[(j0 + r) * DD + k0 + kc + k];
      *(uint4*)&Bl[r][k] = *(const uint4*)&g_Bl[(j0 + r) * DD + k0 + kc + k];
    }
    __syncthreads();
    #pragma unroll
    for (int kk = 0; kk < 64; kk += 16) {
      wmma::fragment<wmma::matrix_a, 16, 16, 16, __nv_bfloat16, wmma::row_major> ah, al;
      wmma::load_matrix_sync(ah, &Ah[wm * 16][kk], 72);
      wmma::load_matrix_sync(al, &Al[wm * 16][kk], 72);
      #pragma unroll
      for (int t = 0; t < 2; t++) {
        int n = wn * 32 + t * 16;
        wmma::fragment<wmma::matrix_b, 16, 16, 16, __nv_bfloat16, wmma::col_major> bh, bl;
        wmma::load_matrix_sync(bh, &Bh[n][kk], 72);
        wmma::load_matrix_sync(bl, &Bl[n][kk], 72);
        wmma::mma_sync(acc[t], ah, bh, acc[t]);
        wmma::mma_sync(acc[t], ah, bl, acc[t]);
        wmma::mma_sync(acc[t], al, bh, acc[t]);
      }
    }
    __syncthreads();
  }
  float* Up = g_Up + z * (HD * N);
  #pragma unroll
  for (int t = 0; t < 2; t++)
    wmma::store_matrix_sync(&Up[(m0 + wm * 16) * N + j0 + wn * 32 + t * 16],
                            acc[t], N, wmma::mem_row_major);
}

// ============ kUred: reduce partials + emit U bf16 split ===================
__global__ void kUred() {
  int idx = blockIdx.x * blockDim.x + threadIdx.x;
  float s = 0.f;
  #pragma unroll
  for (int z = 0; z < ZU; z++) s += g_Up[z * (HD * N) + idx];
  __nv_bfloat16 h = __float2bfloat16(s);
  g_Uh[idx] = h;
  g_Ul[idx] = __float2bfloat16(s - __bfloat162float(h));
}

// ========= kXg: fused GAT-1 softmax + xg = P@x, emit bf16 split ============
__global__ __launch_bounds__(128) void kXg(const float* __restrict__ x) {
  int t = blockIdx.x, tid = threadIdx.x;
  __shared__ int   ss[256];
  __shared__ float sw[256];
  __shared__ float sh[4];
  int p0 = g_offT[t], p1 = g_offT[t + 1];
  float dt = g_da[t];
  float m = -3.4e38f;
  for (int p = p0 + tid; p < p1; p += 128)
    m = fmaxf(m, lrelu(g_sa[g_srcT[p]] + dt));
  #pragma unroll
  for (int o = 16; o; o >>= 1) m = fmaxf(m, __shfl_xor_sync(0xFFFFFFFFu, m, o));
  if ((tid & 31) == 0) sh[tid >> 5] = m;
  __syncthreads();
  m = fmaxf(fmaxf(sh[0], sh[1]), fmaxf(sh[2], sh[3]));
  float acc = 0.f, dsum = 0.f;
  for (int base = p0; base < p1; base += 256) {
    int nc = min(256, p1 - base);
    for (int q = tid; q < nc; q += 128) {
      int s = g_srcT[base + q];
      float w = expf(lrelu(g_sa[s] + dt) - m);
      ss[q] = s;
      sw[q] = w;
      dsum += w;
    }
    __syncthreads();
    for (int q = 0; q < nc; q++)
      acc += sw[q] * x[ss[q] * HD + tid];
    __syncthreads();
  }
  float den = dsum;
  #pragma unroll
  for (int o = 16; o; o >>= 1) den += __shfl_xor_sync(0xFFFFFFFFu, den, o);
  if ((tid & 31) == 0) sh[tid >> 5] = den;
  __syncthreads();
  den = sh[0] + sh[1] + sh[2] + sh[3];
  float xv = acc / den;
  __nv_bfloat16 h = __float2bfloat16(xv);
  g_xgh[t * HD + tid] = h;
  g_xgl[t * HD + tid] = __float2bfloat16(xv - __bfloat162float(h));
}

// == kH2: H2 = xg @ U via WMMA 3-term split; 64x64 tiles ====================
__global__ __launch_bounds__(256, 2) void kH2() {
  __shared__ __align__(16) __nv_bfloat16 Ah[64][72];
  __shared__ __align__(16) __nv_bfloat16 Al[64][72];
  __shared__ __align__(16) __nv_bfloat16 Bh[64][72];
  __shared__ __align__(16) __nv_bfloat16 Bl[64][72];
  int b = blockIdx.x;
  int j0 = (b % 24) * 64;
  int m0 = (b / 24) * 64;
  int tid = threadIdx.x;
  int wid = tid >> 5;
  int wm = wid >> 1;
  int wn = wid & 1;

  wmma::fragment<wmma::accumulator, 16, 16, 16, float> acc[2];
  wmma::fill_fragment(acc[0], 0.f);
  wmma::fill_fragment(acc[1], 0.f);

  for (int kc = 0; kc < HD; kc += 64) {
    for (int l = tid; l < 64 * 8; l += 256) {
      int r = l >> 3, k = (l & 7) * 8;
      *(uint4*)&Ah[r][k] = *(const uint4*)&g_xgh[(m0 + r) * HD + kc + k];
      *(uint4*)&Al[r][k] = *(const uint4*)&g_xgl[(m0 + r) * HD + kc + k];
      *(uint4*)&Bh[r][k] = *(const uint4*)&g_Uh[(kc + r) * N + j0 + k];
      *(uint4*)&Bl[r][k] = *(const uint4*)&g_Ul[(kc + r) * N + j0 + k];
    }
    __syncthreads();
    #pragma unroll
    for (int kk = 0; kk < 64; kk += 16) {
      wmma::fragment<wmma::matrix_a, 16, 16, 16, __nv_bfloat16, wmma::row_major> ah, al;
      wmma::load_matrix_sync(ah, &Ah[wm * 16][kk], 72);
      wmma::load_matrix_sync(al, &Al[wm * 16][kk], 72);
      #pragma unroll
      for (int t = 0; t < 2; t++) {
        int n = wn * 32 + t * 16;
        wmma::fragment<wmma::matrix_b, 16, 16, 16, __nv_bfloat16, wmma::row_major> bh, bl;
        wmma::load_matrix_sync(bh, &Bh[kk][n], 72);
        wmma::load_matrix_sync(bl, &Bl[kk][n], 72);
        wmma::mma_sync(acc[t], ah, bh, acc[t]);
        wmma::mma_sync(acc[t], ah, bl, acc[t]);
        wmma::mma_sync(acc[t], al, bh, acc[t]);
      }
    }
    __syncthreads();
  }
  #pragma unroll
  for (int t = 0; t < 2; t++)
    wmma::store_matrix_sync(&g_H2[(m0 + wm * 16) * N + j0 + wn * 32 + t * 16],
                            acc[t], N, wmma::mem_row_major);
}

// == kF: 2-hop mask (u64) + single-pass factorized gather + radix-select ====
__global__ __launch_bounds__(256) void kF(const float* __restrict__ pas2,
                                          const float* __restrict__ pad2,
                                          const float* __restrict__ pb2,
                                          float* __restrict__ out, int wk) {
  int i = blockIdx.x, tid = threadIdx.x;
  __shared__ float v[N];
  __shared__ int vlist[N];
  __shared__ float scl[N];
  __shared__ unsigned k32[N];
  __shared__ float Ev[N];
  __shared__ float E5v[N];
  __shared__ __align__(8) unsigned mb[NW];
  __shared__ int wcnt[NW + 1];
  __shared__ int hist[256];
  __shared__ float shm[8];
  __shared__ unsigned s_pfx;
  __shared__ int s_rem;
  __shared__ float s_M;

  float as2 = pas2[0], ad2 = pad2[0], b2 = pb2[0];

  if (tid < NW) {
    unsigned w = g_B[i * NW + tid];
    if (tid == (i >> 5)) w |= 1u << (i & 31);
    mb[tid] = w;
  }
  {
    const float4* h2a = (const float4*)(g_H2 + i * N);
    const float4* c2v = (const float4*)g_c2;
    float4* vv = (float4*)v;
    for (int j = tid; j < N / 4; j += 256) {
      float4 a = h2a[j], c = c2v[j];
      vv[j] = make_float4(a.x + c.x, a.y + c.y, a.z + c.z, a.w + c.w);
    }
  }
  __syncthreads();
  if (tid < NW) wcnt[tid] = __popc(mb[tid]);
  __syncthreads();
  if (tid == 0) {
    int s = 0;
    for (int w = 0; w < NW; w++) { int c = wcnt[w]; wcnt[w] = s; s += c; }
    wcnt[NW] = s;
  }
  __syncthreads();
  int nk = wcnt[NW];
  if (tid < NW) {
    unsigned b = mb[tid]; int o = wcnt[tid];
    while (b) { int t = __ffs(b) - 1; b &= b - 1; vlist[o++] = tid * 32 + t; }
  }
  __syncthreads();
  if (tid < 8 * (NW / 2)) {
    int sy = tid / (NW / 2), cx = tid % (NW / 2);
    const unsigned long long* B64 = (const unsigned long long*)g_B;
    unsigned long long acc = 0ull;
    for (int q = sy; q < nk; q += 8) acc |= B64[vlist[q] * (NW / 2) + cx];
    atomicOr(&mb[cx * 2], (unsigned)acc);
    atomicOr(&mb[cx * 2 + 1], (unsigned)(acc >> 32));
  }
  __syncthreads();
  if (tid < NW) wcnt[tid] = __popc(mb[tid]);
  __syncthreads();
  if (tid == 0) {
    int s = 0;
    for (int w = 0; w < NW; w++) { int c = wcnt[w]; wcnt[w] = s; s += c; }
    wcnt[NW] = s;
  }
  __syncthreads();
  int nvv = wcnt[NW];
  if (tid < NW) {
    unsigned b = mb[tid]; int o = wcnt[tid];
    while (b) { int t = __ffs(b) - 1; b &= b - 1; vlist[o++] = tid * 32 + t; }
  }
  __syncthreads();
  {
    float lm = -3.4e38f;
    for (int li = tid; li < nvv; li += 256)
      lm = fmaxf(lm, as2 * v[vlist[li]]);
    #pragma unroll
    for (int o = 16; o; o >>= 1) lm = fmaxf(lm, __shfl_xor_sync(0xFFFFFFFFu, lm, o));
    if ((tid & 31) == 0) shm[tid >> 5] = lm;
    __syncthreads();
    if (tid == 0) {
      float mm = shm[0];
      #pragma unroll
      for (int q = 1; q < 8; q++) mm = fmaxf(mm, shm[q]);
      s_M = mm;
    }
    __syncthreads();
  }
  float M = s_M;
  for (int li = tid; li < nvv; li += 256) {
    int s = vlist[li];
    float a = as2 * v[s] - M;
    Ev[s]  = __expf(a);
    E5v[s] = __expf(0.2f * a);
  }
  __syncthreads();
  for (int li = tid; li < nvv; li += 256) {
    int t = vlist[li];
    int p0 = g_offT[t], p1 = g_offT[t + 1];
    float adt = ad2 * v[t];
    float am = adt + M;
    float m = fmaxf(am, 0.f);
    float F1 = __expf(am - m);
    float F5 = __expf(0.2f * am - m);
    float den = 0.f, num = 0.f;
    for (int p = p0; p < p1; p++) {
      int s = g_srcT[p];
      if ((mb[s >> 5] >> (s & 31)) & 1u) {
        float vs = v[s];
        float u = fmaf(as2, vs, adt);
        float w = (u > 0.f) ? Ev[s] * F1 : E5v[s] * F5;
        den += w;
        num = fmaf(w, vs, num);
      }
    }
    if (den < 1e-30f) {
      float mm = -3.4e38f;
      for (int p = p0; p < p1; p++) {
        int s = g_srcT[p];
        if ((mb[s >> 5] >> (s & 31)) & 1u)
          mm = fmaxf(mm, lrelu(fmaf(as2, v[s], adt)));
      }
      den = 0.f; num = 0.f;
      for (int p = p0; p < p1; p++) {
        int s = g_srcT[p];
        if ((mb[s >> 5] >> (s & 31)) & 1u) {
          float vs = v[s];
          float w = __expf(lrelu(fmaf(as2, vs, adt)) - mm);
          den += w;
          num = fmaf(w, vs, num);
        }
      }
    }
    float sc = num / fmaxf(den, 1e-12f) + b2;
    scl[li] = sc;
    k32[li] = fenc(sc);
  }
  int kk = (nvv + 1) >> 1;
  if (tid == 0) { s_rem = kk; s_pfx = 0u; }
  __syncthreads();
  for (int r = 0; r < 4; r++) {
    int shift = 24 - 8 * r;
    hist[tid] = 0;
    __syncthreads();
    unsigned pfx = s_pfx;
    for (int li = tid; li < nvv; li += 256) {
      unsigned key = k32[li];
      bool cand = (r == 0) || ((key >> (shift + 8)) == pfx);
      if (cand) atomicAdd(&hist[(key >> shift) & 255], 1);
    }
    __syncthreads();
    if (tid < 32) {
      int s = 0;
      #pragma unroll
      for (int u = 0; u < 8; u++) s += hist[tid * 8 + u];
      int cum = s;
      #pragma unroll
      for (int o = 1; o < 32; o <<= 1) {
        int t2 = __shfl_down_sync(0xFFFFFFFFu, cum, o);
        if (tid + o < 32) cum += t2;
      }
      int run = cum - s;
      int rem = s_rem;
      unsigned pfxold = s_pfx;
      int fb = -1, frem = 0;
      for (int bb = tid * 8 + 7; bb >= tid * 8; bb--) {
        int h = hist[bb];
        if (run < rem && rem <= run + h) { fb = bb; frem = rem - run; }
        run += h;
      }
      __syncwarp();
      if (fb >= 0) { s_pfx = (pfxold << 8) | (unsigned)fb; s_rem = frem; }
    }
    __syncthreads();
  }
  unsigned T = s_pfx;
  int rem = s_rem;
  for (int li = tid; li < nvv; li += 256) {
    unsigned key = k32[li];
    bool keep = key > T;
    if (!keep && key == T) {
      int cnt = 0;
      for (int l2 = 0; l2 < li; l2++) cnt += (k32[l2] == T);
      keep = cnt < rem;
    }
    if (keep) {
      int j = vlist[li];
      float sj = scl[li];
      out[i * N + j] = 1.f / (1.f + __expf(-sj));
      if (wk) out[N * N + i * N + j] = 1.f;
    }
  }
}

// ---------------- launch: forked-capture graph ----------------
extern "C" void kernel_launch(void* const* d_in, const int* in_sizes, int n_in,
                              void* d_out, int out_size) {
  const float* x   = (const float*)d_in[0];
  const float* xo  = (const float*)d_in[1];
  const int*   ei  = (const int*)d_in[2];
  const float* W1  = (const float*)d_in[4];
  const float* a1  = (const float*)d_in[5];
  const float* a2  = (const float*)d_in[6];
  const float* b1  = (const float*)d_in[7];
  const float* w2  = (const float*)d_in[8];
  const float* as2 = (const float*)d_in[9];
  const float* ad2 = (const float*)d_in[10];
  const float* b2  = (const float*)d_in[11];
  float* out = (float*)d_out;
  int wk = (out_size >= 2 * N * N) ? 1 : 0;

  cudaEventRecord(g_hs.e0, 0);
  cudaStreamWaitEvent(g_hs.s1, g_hs.e0, 0);
  cudaStreamWaitEvent(g_hs.s2, g_hs.e0, 0);
  cudaStreamWaitEvent(g_hs.s3, g_hs.e0, 0);

  // s3: zero out + g_B
  kZero<<<512, 256, 0, g_hs.s3>>>(out, out_size);
  cudaEventRecord(g_hs.e3, g_hs.s3);

  // s1: vec1 -> sada
  kVec1<<<HD + N, 256, 0, g_hs.s1>>>(W1, a1, a2, b1, w2, xo);
  kSada<<<192, 256, 0, g_hs.s1>>>(x);
  cudaEventRecord(g_hs.e1, g_hs.s1);

  // s2: split (vectorized) -> U partials (WMMA) -> U reduce+split
  kSplit<<<592, 256, 0, g_hs.s2>>>(W1, w2, xo);
  kUp<<<48 * ZU, 256, 0, g_hs.s2>>>();
  kUred<<<(HD * N) / 256, 256, 0, g_hs.s2>>>();
  cudaEventRecord(g_hs.e2, g_hs.s2);

  // s0 (default): critical path
  kCount<<<E2 / 256, 256>>>(ei);
  kScan<<<1, 256>>>();
  cudaStreamWaitEvent(0, g_hs.e3, 0);   // g_B zeroed before fill's atomicOr
  kFill<<<E2 / 256, 256>>>(ei);
  cudaStreamWaitEvent(0, g_hs.e1, 0);   // sada done before xg
  kXg<<<N, 128>>>(x);
  cudaStreamWaitEvent(0, g_hs.e2, 0);   // U ready before H2
  kH2<<<576, 256>>>();
  kF<<<N, 256>>>(as2, ad2, b2, out, wk);
}